// round 1
// baseline (speedup 1.0000x reference)
#include <cuda_runtime.h>

// ---------------------------------------------------------------------------
// point_transformer fused kernel, Round 1 (fp32 SIMT baseline)
// ---------------------------------------------------------------------------
#define NMAX 50000
#define HH   16

// Scratch (device globals: allocation-free per harness rules)
__device__ float g_qkv[NMAX * 768];     // [n][0:256)=q [256:512)=k [512:768)=v
__device__ int   g_inds[NMAX * HH];
__device__ int   g_is32;
__device__ float g_wcat[256 * 768];
__device__ float g_bcat[768];

static __device__ __forceinline__ float lrelu(float x) {
    return fmaxf(x, 0.1f * x);
}

// --------------------------- index dtype handling ---------------------------
__global__ void pt_detect_idx(const unsigned* __restrict__ w) {
    __shared__ int flag;
    if (threadIdx.x == 0) flag = 0;
    __syncthreads();
    // If indices are int64 (values < 2^31, non-negative), every odd 32-bit
    // word is zero. If int32, odd words are actual random indices.
    unsigned v = w[2 * threadIdx.x + 1];
    if (v != 0u) flag = 1;
    __syncthreads();
    if (threadIdx.x == 0) g_is32 = flag;
}

__global__ void pt_convert_idx(const void* __restrict__ p, int total) {
    int i = blockIdx.x * blockDim.x + threadIdx.x;
    if (i >= total) return;
    if (g_is32) g_inds[i] = ((const int*)p)[i];
    else        g_inds[i] = (int)(((const long long*)p)[i]);
}

// --------------------------- weight prepack --------------------------------
__global__ void pt_prepack(const float* __restrict__ Wq, const float* __restrict__ bq,
                           const float* __restrict__ Wk, const float* __restrict__ bk,
                           const float* __restrict__ Wv, const float* __restrict__ bv) {
    int i = blockIdx.x * blockDim.x + threadIdx.x;
    if (i < 256 * 768) {
        int ci = i / 768, co = i % 768;
        float v;
        if      (co < 256) v = Wq[ci * 256 + co];
        else if (co < 512) v = Wk[ci * 256 + (co - 256)];
        else               v = Wv[ci * 256 + (co - 512)];
        g_wcat[i] = v;
    }
    if (i < 768) {
        g_bcat[i] = (i < 256) ? bq[i] : (i < 512 ? bk[i - 256] : bv[i - 512]);
    }
}

// --------------------------- QKV GEMM ---------------------------------------
// C[M,768] = A[M,256] @ Wcat[256,768] + bcat.  128x128 tile, 8x8 microtile.
__global__ void __launch_bounds__(256, 2)
pt_qkv_gemm(const float* __restrict__ A, int M) {
    __shared__ float As[2][16][128];   // [buf][k][m]
    __shared__ float Bs[2][16][128];   // [buf][k][n]

    const int t  = threadIdx.x;
    const int m0 = blockIdx.x * 128;
    const int n0 = blockIdx.y * 128;
    const int tx = t & 15;
    const int ty = t >> 4;

    const int ar = t >> 2;          // 0..63
    const int ac = (t & 3) * 4;     // 0,4,8,12
    const int br = t >> 5;          // 0..7
    const int bc = (t & 31) * 4;

    float4 a0, a1, b0, b1;

    // preload k-tile 0
    {
        const int k0 = 0;
        a0 = (m0 + ar      < M) ? *(const float4*)&A[(m0 + ar     ) * 256 + k0 + ac] : make_float4(0.f,0.f,0.f,0.f);
        a1 = (m0 + ar + 64 < M) ? *(const float4*)&A[(m0 + ar + 64) * 256 + k0 + ac] : make_float4(0.f,0.f,0.f,0.f);
        b0 = *(const float4*)&g_wcat[(k0 + br    ) * 768 + n0 + bc];
        b1 = *(const float4*)&g_wcat[(k0 + br + 8) * 768 + n0 + bc];
        As[0][ac+0][ar] = a0.x; As[0][ac+1][ar] = a0.y; As[0][ac+2][ar] = a0.z; As[0][ac+3][ar] = a0.w;
        As[0][ac+0][ar+64] = a1.x; As[0][ac+1][ar+64] = a1.y; As[0][ac+2][ar+64] = a1.z; As[0][ac+3][ar+64] = a1.w;
        *(float4*)&Bs[0][br    ][bc] = b0;
        *(float4*)&Bs[0][br + 8][bc] = b1;
    }
    __syncthreads();

    float acc[8][8];
    #pragma unroll
    for (int i = 0; i < 8; i++)
        #pragma unroll
        for (int j = 0; j < 8; j++) acc[i][j] = 0.f;

    for (int kt = 0; kt < 16; kt++) {
        const int cur = kt & 1;
        if (kt < 15) {
            const int k0 = (kt + 1) * 16;
            a0 = (m0 + ar      < M) ? *(const float4*)&A[(m0 + ar     ) * 256 + k0 + ac] : make_float4(0.f,0.f,0.f,0.f);
            a1 = (m0 + ar + 64 < M) ? *(const float4*)&A[(m0 + ar + 64) * 256 + k0 + ac] : make_float4(0.f,0.f,0.f,0.f);
            b0 = *(const float4*)&g_wcat[(k0 + br    ) * 768 + n0 + bc];
            b1 = *(const float4*)&g_wcat[(k0 + br + 8) * 768 + n0 + bc];
        }
        #pragma unroll
        for (int kk = 0; kk < 16; kk++) {
            float4 av0 = *(const float4*)&As[cur][kk][ty * 8];
            float4 av1 = *(const float4*)&As[cur][kk][ty * 8 + 4];
            float4 bv0 = *(const float4*)&Bs[cur][kk][tx * 8];
            float4 bv1 = *(const float4*)&Bs[cur][kk][tx * 8 + 4];
            float av[8] = {av0.x, av0.y, av0.z, av0.w, av1.x, av1.y, av1.z, av1.w};
            float bv[8] = {bv0.x, bv0.y, bv0.z, bv0.w, bv1.x, bv1.y, bv1.z, bv1.w};
            #pragma unroll
            for (int i = 0; i < 8; i++)
                #pragma unroll
                for (int j = 0; j < 8; j++)
                    acc[i][j] += av[i] * bv[j];
        }
        if (kt < 15) {
            const int nxt = cur ^ 1;
            As[nxt][ac+0][ar] = a0.x; As[nxt][ac+1][ar] = a0.y; As[nxt][ac+2][ar] = a0.z; As[nxt][ac+3][ar] = a0.w;
            As[nxt][ac+0][ar+64] = a1.x; As[nxt][ac+1][ar+64] = a1.y; As[nxt][ac+2][ar+64] = a1.z; As[nxt][ac+3][ar+64] = a1.w;
            *(float4*)&Bs[nxt][br    ][bc] = b0;
            *(float4*)&Bs[nxt][br + 8][bc] = b1;
        }
        __syncthreads();
    }

    // epilogue: + bias, store
    float4 bb0 = *(const float4*)&g_bcat[n0 + tx * 8];
    float4 bb1 = *(const float4*)&g_bcat[n0 + tx * 8 + 4];
    #pragma unroll
    for (int i = 0; i < 8; i++) {
        int row = m0 + ty * 8 + i;
        if (row < M) {
            float4 o0 = make_float4(acc[i][0] + bb0.x, acc[i][1] + bb0.y,
                                    acc[i][2] + bb0.z, acc[i][3] + bb0.w);
            float4 o1 = make_float4(acc[i][4] + bb1.x, acc[i][5] + bb1.y,
                                    acc[i][6] + bb1.z, acc[i][7] + bb1.w);
            *(float4*)&g_qkv[row * 768 + n0 + tx * 8    ] = o0;
            *(float4*)&g_qkv[row * 768 + n0 + tx * 8 + 4] = o1;
        }
    }
}

// --------------------------- fused attention --------------------------------
// One point per CTA iteration; 256 threads; thread t owns channel c = t.
// Shared layout (floats):
#define OFF_WD2   0        // [64][256]
#define OFF_WA1   16384    // [256][32]
#define OFF_WA2   24576    // [32][32]
#define OFF_WD1   25600    // [3][64]
#define OFF_BD1   25792    // 64
#define OFF_BD2   25856    // 256
#define OFF_BA1   26112    // 32
#define OFF_BA2   26144    // 32
#define OFF_HID   26176    // [64][16]
#define OFF_ASH   27200    // [16][260]  (pad for bank-conflict-free + 16B align)
#define OFF_VMG   31360    // [16][256]
#define OFF_L1    35456    // [16][34]
#define OFF_L2    36000    // [16][34]
#define OFF_ATTN  36544    // [16][34]
#define OFF_INDS  37088    // 16 ints
#define OFF_QPT   37104    // 3 floats
#define SMEM_FLOATS 37120
#define SMEM_BYTES  (SMEM_FLOATS * 4)

__global__ void __launch_bounds__(256, 1)
pt_fused_attn(const float* __restrict__ q_pts,
              const float* __restrict__ s_pts,
              const float* __restrict__ Wd1, const float* __restrict__ bd1,
              const float* __restrict__ Wd2, const float* __restrict__ bd2,
              const float* __restrict__ Wa1, const float* __restrict__ ba1,
              const float* __restrict__ Wa2, const float* __restrict__ ba2,
              float* __restrict__ out, int N) {
    extern __shared__ float sm[];
    float* Wd2s = sm + OFF_WD2;
    float* Wa1s = sm + OFF_WA1;
    float* Wa2s = sm + OFF_WA2;
    float* Wd1s = sm + OFF_WD1;
    float* bd1s = sm + OFF_BD1;
    float* bd2s = sm + OFF_BD2;
    float* ba1s = sm + OFF_BA1;
    float* ba2s = sm + OFF_BA2;
    float* hid  = sm + OFF_HID;
    float* a_sh = sm + OFF_ASH;
    float* vmg  = sm + OFF_VMG;
    float* l1s  = sm + OFF_L1;
    float* l2s  = sm + OFF_L2;
    float* attn = sm + OFF_ATTN;
    int*   inds_s = (int*)(sm + OFF_INDS);
    float* qptf   = sm + OFF_QPT;

    const int t = threadIdx.x;

    // stage 0: weights -> shared (once per CTA)
    for (int i = t; i < 16384; i += 256) Wd2s[i] = Wd2[i];
    for (int i = t; i < 8192;  i += 256) Wa1s[i] = Wa1[i];
    for (int i = t; i < 1024;  i += 256) Wa2s[i] = Wa2[i];
    if (t < 192) Wd1s[t] = Wd1[t];
    if (t < 64)  bd1s[t] = bd1[t];
    bd2s[t] = bd2[t];
    if (t < 32) { ba1s[t] = ba1[t]; ba2s[t] = ba2[t]; }
    __syncthreads();

    for (int n = blockIdx.x; n < N; n += gridDim.x) {
        __syncthreads();   // protect per-point smem vs previous iteration readers
        if (t < 16) inds_s[t] = g_inds[n * 16 + t];
        if (t < 3)  qptf[t]   = q_pts[n * 3 + t];
        __syncthreads();

        // stage 1: hidden[64][16] = lrelu(rel @ Wd1 + bd1), stored [d][h]
        {
            const int h  = t >> 4;
            const int d0 = (t & 15) << 2;
            const int j  = inds_s[h];
            const float rx = s_pts[j * 3 + 0] - qptf[0];
            const float ry = s_pts[j * 3 + 1] - qptf[1];
            const float rz = s_pts[j * 3 + 2] - qptf[2];
            #pragma unroll
            for (int i = 0; i < 4; i++) {
                const int d = d0 + i;
                float v = rx * Wd1s[d] + ry * Wd1s[64 + d] + rz * Wd1s[128 + d] + bd1s[d];
                hid[d * 16 + h] = lrelu(v);
            }
        }
        __syncthreads();

        // stage 2: geom[h][c=t] accumulated in registers (1024 FMA/thread)
        float g[16];
        {
            const float b2 = bd2s[t];
            #pragma unroll
            for (int h = 0; h < 16; h++) g[h] = b2;
            #pragma unroll 4
            for (int d = 0; d < 64; d++) {
                const float w = Wd2s[d * 256 + t];
                const float4* hp = (const float4*)(hid + d * 16);
                float4 h0 = hp[0], h1 = hp[1], h2 = hp[2], h3 = hp[3];
                g[0]  += w * h0.x; g[1]  += w * h0.y; g[2]  += w * h0.z; g[3]  += w * h0.w;
                g[4]  += w * h1.x; g[5]  += w * h1.y; g[6]  += w * h1.z; g[7]  += w * h1.w;
                g[8]  += w * h2.x; g[9]  += w * h2.y; g[10] += w * h2.z; g[11] += w * h2.w;
                g[12] += w * h3.x; g[13] += w * h3.y; g[14] += w * h3.z; g[15] += w * h3.w;
            }
        }

        // stage 3: gathers (coalesced), qk -> a, nv-geom -> vmg
        {
            const int j0 = inds_s[0];
            const float qf = g_qkv[j0 * 768 + t];
            #pragma unroll
            for (int h = 0; h < 16; h++) {
                const int j = inds_s[h];
                const float nk = g_qkv[j * 768 + 256 + t];
                const float nv = g_qkv[j * 768 + 512 + t];
                const float qk = qf - nk - g[h];
                a_sh[h * 260 + t] = lrelu(qk);
                vmg [h * 256 + t] = nv - g[h];
            }
        }
        __syncthreads();

        // stage 4: logits1 = lrelu(a @ Wa1 + ba1); thread -> (h = t>>4, m0 = 2*(t&15))
        {
            const int h  = t >> 4;
            const int m0 = (t & 15) * 2;
            float acc0 = ba1s[m0];
            float acc1 = ba1s[m0 + 1];
            const float* arow = a_sh + h * 260;
            #pragma unroll 8
            for (int c = 0; c < 256; c += 4) {
                float4 av = *(const float4*)(arow + c);
                float2 w0 = *(const float2*)(Wa1s + (c + 0) * 32 + m0);
                float2 w1 = *(const float2*)(Wa1s + (c + 1) * 32 + m0);
                float2 w2 = *(const float2*)(Wa1s + (c + 2) * 32 + m0);
                float2 w3 = *(const float2*)(Wa1s + (c + 3) * 32 + m0);
                acc0 += av.x * w0.x + av.y * w1.x + av.z * w2.x + av.w * w3.x;
                acc1 += av.x * w0.y + av.y * w1.y + av.z * w2.y + av.w * w3.y;
            }
            l1s[h * 34 + m0    ] = lrelu(acc0);
            l1s[h * 34 + m0 + 1] = lrelu(acc1);
        }
        __syncthreads();

        // stage 5: logits2 = l1 @ Wa2 + ba2
        {
            const int h  = t >> 4;
            const int m0 = (t & 15) * 2;
            float acc0 = ba2s[m0];
            float acc1 = ba2s[m0 + 1];
            const float* lrow = l1s + h * 34;
            #pragma unroll
            for (int jj = 0; jj < 32; jj++) {
                const float lv = lrow[jj];
                float2 w = *(const float2*)(Wa2s + jj * 32 + m0);
                acc0 += lv * w.x;
                acc1 += lv * w.y;
            }
            l2s[h * 34 + m0    ] = acc0;
            l2s[h * 34 + m0 + 1] = acc1;
        }
        __syncthreads();

        // stage 6: softmax over h (axis=1), one lane per m
        if (t < 32) {
            float vals[16];
            float mx = -3.4e38f;
            #pragma unroll
            for (int h = 0; h < 16; h++) {
                vals[h] = l2s[h * 34 + t];
                mx = fmaxf(mx, vals[h]);
            }
            float s = 0.f;
            #pragma unroll
            for (int h = 0; h < 16; h++) {
                vals[h] = __expf(vals[h] - mx);
                s += vals[h];
            }
            const float inv = 1.f / s;
            #pragma unroll
            for (int h = 0; h < 16; h++) attn[h * 34 + t] = vals[h] * inv;
        }
        __syncthreads();

        // stage 7: out[c] = sum_h vmg[h][c] * attn[h][c>>3]
        {
            float acc = 0.f;
            const int mg = t >> 3;
            #pragma unroll
            for (int h = 0; h < 16; h++)
                acc += vmg[h * 256 + t] * attn[h * 34 + mg];
            out[n * 256 + t] = acc;
        }
    }
}

// --------------------------- launch ------------------------------------------
extern "C" void kernel_launch(void* const* d_in, const int* in_sizes, int n_in,
                              void* d_out, int out_size) {
    const float* q_pts   = (const float*)d_in[0];
    const float* s_pts   = (const float*)d_in[1];
    const float* s_feats = (const float*)d_in[2];
    const void*  nb_inds = d_in[3];
    const float* Wq = (const float*)d_in[4];
    const float* bq = (const float*)d_in[5];
    const float* Wk = (const float*)d_in[6];
    const float* bk = (const float*)d_in[7];
    const float* Wv = (const float*)d_in[8];
    const float* bv = (const float*)d_in[9];
    const float* Wd1 = (const float*)d_in[10];
    const float* bd1 = (const float*)d_in[11];
    const float* Wd2 = (const float*)d_in[12];
    const float* bd2 = (const float*)d_in[13];
    const float* Wa1 = (const float*)d_in[14];
    const float* ba1 = (const float*)d_in[15];
    const float* Wa2 = (const float*)d_in[16];
    const float* ba2 = (const float*)d_in[17];
    float* out = (float*)d_out;

    const int N = in_sizes[0] / 3;

    cudaFuncSetAttribute(pt_fused_attn,
                         cudaFuncAttributeMaxDynamicSharedMemorySize, SMEM_BYTES);

    // 1) canonicalize indices (int64-or-int32 -> int32)
    pt_detect_idx<<<1, 256>>>((const unsigned*)nb_inds);
    pt_convert_idx<<<(N * HH + 255) / 256, 256>>>(nb_inds, N * HH);

    // 2) prepack concatenated QKV weights
    pt_prepack<<<(256 * 768 + 255) / 256, 256>>>(Wq, bq, Wk, bk, Wv, bv);

    // 3) QKV GEMM
    dim3 ggrid((N + 127) / 128, 6);
    pt_qkv_gemm<<<ggrid, 256>>>(s_feats, N);

    // 4) fused geometric attention
    int fgrid = 1480;
    if (fgrid > N) fgrid = N;
    pt_fused_attn<<<fgrid, 256, SMEM_BYTES>>>(q_pts, s_pts,
                                              Wd1, bd1, Wd2, bd2,
                                              Wa1, ba1, Wa2, ba2,
                                              out, N);
}

// round 2
// speedup vs baseline: 1.2083x; 1.2083x over previous
#include <cuda_runtime.h>

// ---------------------------------------------------------------------------
// point_transformer fused kernel, Round 2
//   - f32x2 packed FFMA (FFMA2) in all hot loops
//   - 512-thread fused CTA processing 2 points/iter (16 warps/SM)
// ---------------------------------------------------------------------------
#define NMAX 50000
#define HH   16

typedef unsigned long long ull;

// Scratch (device globals: allocation-free per harness rules)
__device__ float g_qkv[NMAX * 768];     // [n][0:256)=q [256:512)=k [512:768)=v
__device__ int   g_inds[NMAX * HH];
__device__ int   g_is32;
__device__ float g_wcat[256 * 768];
__device__ float g_bcat[768];

static __device__ __forceinline__ float lrelu(float x) {
    return fmaxf(x, 0.1f * x);
}

static __device__ __forceinline__ ull ffma2(ull a, ull b, ull c) {
    ull d;
    asm("fma.rn.f32x2 %0, %1, %2, %3;" : "=l"(d) : "l"(a), "l"(b), "l"(c));
    return d;
}
static __device__ __forceinline__ ull pack2(float x, float y) {
    ull r;
    asm("mov.b64 %0, {%1, %2};" : "=l"(r) : "f"(x), "f"(y));
    return r;
}
static __device__ __forceinline__ float2 unpack2(ull v) {
    float2 f;
    asm("mov.b64 {%0, %1}, %2;" : "=f"(f.x), "=f"(f.y) : "l"(v));
    return f;
}

// --------------------------- index dtype handling ---------------------------
__global__ void pt_detect_idx(const unsigned* __restrict__ w) {
    __shared__ int flag;
    if (threadIdx.x == 0) flag = 0;
    __syncthreads();
    // int64 indices (values < 2^31, non-negative): every odd 32-bit word is 0.
    unsigned v = w[2 * threadIdx.x + 1];
    if (v != 0u) flag = 1;
    __syncthreads();
    if (threadIdx.x == 0) g_is32 = flag;
}

__global__ void pt_convert_idx(const void* __restrict__ p, int total) {
    int i = blockIdx.x * blockDim.x + threadIdx.x;
    if (i >= total) return;
    if (g_is32) g_inds[i] = ((const int*)p)[i];
    else        g_inds[i] = (int)(((const long long*)p)[i]);
}

// --------------------------- weight prepack --------------------------------
__global__ void pt_prepack(const float* __restrict__ Wq, const float* __restrict__ bq,
                           const float* __restrict__ Wk, const float* __restrict__ bk,
                           const float* __restrict__ Wv, const float* __restrict__ bv) {
    int i = blockIdx.x * blockDim.x + threadIdx.x;
    if (i < 256 * 768) {
        int ci = i / 768, co = i % 768;
        float v;
        if      (co < 256) v = Wq[ci * 256 + co];
        else if (co < 512) v = Wk[ci * 256 + (co - 256)];
        else               v = Wv[ci * 256 + (co - 512)];
        g_wcat[i] = v;
    }
    if (i < 768) {
        g_bcat[i] = (i < 256) ? bq[i] : (i < 512 ? bk[i - 256] : bv[i - 512]);
    }
}

// --------------------------- QKV GEMM ---------------------------------------
// C[M,768] = A[M,256] @ Wcat[256,768] + bcat.  128x128 tile, 8x8 microtile,
// FFMA2 inner product (n-pairs packed straight out of the Bs float4 loads).
__global__ void __launch_bounds__(256, 2)
pt_qkv_gemm(const float* __restrict__ A, int M) {
    __shared__ float As[2][16][128];   // [buf][k][m]
    __shared__ float Bs[2][16][128];   // [buf][k][n]

    const int t  = threadIdx.x;
    const int m0 = blockIdx.x * 128;
    const int n0 = blockIdx.y * 128;
    const int tx = t & 15;
    const int ty = t >> 4;

    const int ar = t >> 2;          // 0..63
    const int ac = (t & 3) * 4;     // 0,4,8,12
    const int br = t >> 5;          // 0..7
    const int bc = (t & 31) * 4;

    float4 a0, a1, b0, b1;

    {
        const int k0 = 0;
        a0 = (m0 + ar      < M) ? *(const float4*)&A[(m0 + ar     ) * 256 + k0 + ac] : make_float4(0.f,0.f,0.f,0.f);
        a1 = (m0 + ar + 64 < M) ? *(const float4*)&A[(m0 + ar + 64) * 256 + k0 + ac] : make_float4(0.f,0.f,0.f,0.f);
        b0 = *(const float4*)&g_wcat[(k0 + br    ) * 768 + n0 + bc];
        b1 = *(const float4*)&g_wcat[(k0 + br + 8) * 768 + n0 + bc];
        As[0][ac+0][ar] = a0.x; As[0][ac+1][ar] = a0.y; As[0][ac+2][ar] = a0.z; As[0][ac+3][ar] = a0.w;
        As[0][ac+0][ar+64] = a1.x; As[0][ac+1][ar+64] = a1.y; As[0][ac+2][ar+64] = a1.z; As[0][ac+3][ar+64] = a1.w;
        *(float4*)&Bs[0][br    ][bc] = b0;
        *(float4*)&Bs[0][br + 8][bc] = b1;
    }
    __syncthreads();

    ull acc2[8][4];
    #pragma unroll
    for (int i = 0; i < 8; i++)
        #pragma unroll
        for (int j = 0; j < 4; j++) acc2[i][j] = 0ull;

    for (int kt = 0; kt < 16; kt++) {
        const int cur = kt & 1;
        if (kt < 15) {
            const int k0 = (kt + 1) * 16;
            a0 = (m0 + ar      < M) ? *(const float4*)&A[(m0 + ar     ) * 256 + k0 + ac] : make_float4(0.f,0.f,0.f,0.f);
            a1 = (m0 + ar + 64 < M) ? *(const float4*)&A[(m0 + ar + 64) * 256 + k0 + ac] : make_float4(0.f,0.f,0.f,0.f);
            b0 = *(const float4*)&g_wcat[(k0 + br    ) * 768 + n0 + bc];
            b1 = *(const float4*)&g_wcat[(k0 + br + 8) * 768 + n0 + bc];
        }
        #pragma unroll
        for (int kk = 0; kk < 16; kk++) {
            float4 av0 = *(const float4*)&As[cur][kk][ty * 8];
            float4 av1 = *(const float4*)&As[cur][kk][ty * 8 + 4];
            ulonglong2 bq0 = *(const ulonglong2*)&Bs[cur][kk][tx * 8];
            ulonglong2 bq1 = *(const ulonglong2*)&Bs[cur][kk][tx * 8 + 4];
            ull bp[4] = {bq0.x, bq0.y, bq1.x, bq1.y};
            float av[8] = {av0.x, av0.y, av0.z, av0.w, av1.x, av1.y, av1.z, av1.w};
            #pragma unroll
            for (int i = 0; i < 8; i++) {
                ull ai = pack2(av[i], av[i]);
                #pragma unroll
                for (int j = 0; j < 4; j++)
                    acc2[i][j] = ffma2(ai, bp[j], acc2[i][j]);
            }
        }
        if (kt < 15) {
            const int nxt = cur ^ 1;
            As[nxt][ac+0][ar] = a0.x; As[nxt][ac+1][ar] = a0.y; As[nxt][ac+2][ar] = a0.z; As[nxt][ac+3][ar] = a0.w;
            As[nxt][ac+0][ar+64] = a1.x; As[nxt][ac+1][ar+64] = a1.y; As[nxt][ac+2][ar+64] = a1.z; As[nxt][ac+3][ar+64] = a1.w;
            *(float4*)&Bs[nxt][br    ][bc] = b0;
            *(float4*)&Bs[nxt][br + 8][bc] = b1;
        }
        __syncthreads();
    }

    float4 bb0 = *(const float4*)&g_bcat[n0 + tx * 8];
    float4 bb1 = *(const float4*)&g_bcat[n0 + tx * 8 + 4];
    #pragma unroll
    for (int i = 0; i < 8; i++) {
        int row = m0 + ty * 8 + i;
        if (row < M) {
            float2 c0 = unpack2(acc2[i][0]);
            float2 c1 = unpack2(acc2[i][1]);
            float2 c2 = unpack2(acc2[i][2]);
            float2 c3 = unpack2(acc2[i][3]);
            float4 o0 = make_float4(c0.x + bb0.x, c0.y + bb0.y, c1.x + bb0.z, c1.y + bb0.w);
            float4 o1 = make_float4(c2.x + bb1.x, c2.y + bb1.y, c3.x + bb1.z, c3.y + bb1.w);
            *(float4*)&g_qkv[row * 768 + n0 + tx * 8    ] = o0;
            *(float4*)&g_qkv[row * 768 + n0 + tx * 8 + 4] = o1;
        }
    }
}

// --------------------------- fused attention --------------------------------
// 512 threads/CTA = two 256-thread halves, each handling one point per iter.
// Weights staged once in shared; per-point blocks duplicated per half.
// Shared layout (floats):
#define OFF_WD2   0        // [64][256]
#define OFF_WA1   16384    // [256][32]
#define OFF_WA2   24576    // [32][32]
#define OFF_WD1   25600    // [3][64]
#define OFF_BD1   25792    // 64
#define OFF_BD2   25856    // 256
#define OFF_BA1   26112    // 32
#define OFF_BA2   26144    // 32
#define WEIGHT_FLOATS 26176

// per-point block offsets (relative)
#define PP_HID    0        // [64][16]
#define PP_ASH    1024     // [16][260]
#define PP_VMG    5184     // [16][256]
#define PP_L1     9280     // [16][34]
#define PP_L2     9824     // [16][34]
#define PP_ATTN   10368    // [16][34]
#define PP_INDS   10912    // 16 ints
#define PP_QPT    10928    // 3 floats
#define PP_FLOATS 10944

#define SMEM_FLOATS (WEIGHT_FLOATS + 2 * PP_FLOATS)
#define SMEM_BYTES  (SMEM_FLOATS * 4)

__global__ void __launch_bounds__(512, 1)
pt_fused_attn(const float* __restrict__ q_pts,
              const float* __restrict__ s_pts,
              const float* __restrict__ Wd1, const float* __restrict__ bd1,
              const float* __restrict__ Wd2, const float* __restrict__ bd2,
              const float* __restrict__ Wa1, const float* __restrict__ ba1,
              const float* __restrict__ Wa2, const float* __restrict__ ba2,
              float* __restrict__ out, int N) {
    extern __shared__ float sm[];
    float* Wd2s = sm + OFF_WD2;
    float* Wa1s = sm + OFF_WA1;
    float* Wa2s = sm + OFF_WA2;
    float* Wd1s = sm + OFF_WD1;
    float* bd1s = sm + OFF_BD1;
    float* bd2s = sm + OFF_BD2;
    float* ba1s = sm + OFF_BA1;
    float* ba2s = sm + OFF_BA2;

    const int t   = threadIdx.x;
    const int pid = t >> 8;        // which point-half
    const int tt  = t & 255;       // thread within half

    float* pp    = sm + WEIGHT_FLOATS + pid * PP_FLOATS;
    float* hid   = pp + PP_HID;
    float* a_sh  = pp + PP_ASH;
    float* vmg   = pp + PP_VMG;
    float* l1s   = pp + PP_L1;
    float* l2s   = pp + PP_L2;
    float* attn  = pp + PP_ATTN;
    int*   inds_s = (int*)(pp + PP_INDS);
    float* qptf   = pp + PP_QPT;

    // stage 0: weights -> shared (once per CTA; all 512 threads)
    for (int i = t; i < 16384; i += 512) Wd2s[i] = Wd2[i];
    for (int i = t; i < 8192;  i += 512) Wa1s[i] = Wa1[i];
    for (int i = t; i < 1024;  i += 512) Wa2s[i] = Wa2[i];
    if (t < 192) Wd1s[t] = Wd1[t];
    if (t < 64)  bd1s[t] = bd1[t];
    if (t < 256) bd2s[t] = bd2[t];
    if (t < 32) { ba1s[t] = ba1[t]; ba2s[t] = ba2[t]; }
    __syncthreads();

    for (int n2 = blockIdx.x; n2 * 2 < N; n2 += gridDim.x) {
        const int nreq = n2 * 2 + pid;
        const int n = (nreq < N) ? nreq : (N - 1);
        const bool do_store = (nreq < N);

        __syncthreads();   // protect per-point smem vs previous iteration readers
        if (tt < 16) inds_s[tt] = g_inds[n * 16 + tt];
        if (tt < 3)  qptf[tt]   = q_pts[n * 3 + tt];
        __syncthreads();

        // stage 1: hidden[64][16] = lrelu(rel @ Wd1 + bd1), stored [d][h]
        {
            const int h  = tt >> 4;
            const int d0 = (tt & 15) << 2;
            const int j  = inds_s[h];
            const float rx = s_pts[j * 3 + 0] - qptf[0];
            const float ry = s_pts[j * 3 + 1] - qptf[1];
            const float rz = s_pts[j * 3 + 2] - qptf[2];
            #pragma unroll
            for (int i = 0; i < 4; i++) {
                const int d = d0 + i;
                float v = rx * Wd1s[d] + ry * Wd1s[64 + d] + rz * Wd1s[128 + d] + bd1s[d];
                hid[d * 16 + h] = lrelu(v);
            }
        }
        __syncthreads();

        // stage 2: geom[h][c=tt], h-pairs packed, FFMA2 (512 packed FMA/thread)
        ull g[8];
        {
            const float b2 = bd2s[tt];
            const ull b2p = pack2(b2, b2);
            #pragma unroll
            for (int hp = 0; hp < 8; hp++) g[hp] = b2p;
            #pragma unroll 4
            for (int d = 0; d < 64; d++) {
                const float w = Wd2s[d * 256 + tt];
                const ull ww = pack2(w, w);
                const ulonglong2* hp4 = (const ulonglong2*)(hid + d * 16);
                ulonglong2 h01 = hp4[0], h23 = hp4[1], h45 = hp4[2], h67 = hp4[3];
                g[0] = ffma2(ww, h01.x, g[0]);
                g[1] = ffma2(ww, h01.y, g[1]);
                g[2] = ffma2(ww, h23.x, g[2]);
                g[3] = ffma2(ww, h23.y, g[3]);
                g[4] = ffma2(ww, h45.x, g[4]);
                g[5] = ffma2(ww, h45.y, g[5]);
                g[6] = ffma2(ww, h67.x, g[6]);
                g[7] = ffma2(ww, h67.y, g[7]);
            }
        }

        // stage 3: gathers (coalesced), qk -> a, nv-geom -> vmg
        {
            const int j0 = inds_s[0];
            const float qf = g_qkv[j0 * 768 + tt];
            #pragma unroll
            for (int hp = 0; hp < 8; hp++) {
                const float2 gp = unpack2(g[hp]);
                const int h0 = hp * 2;
                const int ja = inds_s[h0];
                const int jb = inds_s[h0 + 1];
                const float nka = g_qkv[ja * 768 + 256 + tt];
                const float nva = g_qkv[ja * 768 + 512 + tt];
                const float nkb = g_qkv[jb * 768 + 256 + tt];
                const float nvb = g_qkv[jb * 768 + 512 + tt];
                a_sh[h0 * 260 + tt]       = lrelu(qf - nka - gp.x);
                vmg [h0 * 256 + tt]       = nva - gp.x;
                a_sh[(h0 + 1) * 260 + tt] = lrelu(qf - nkb - gp.y);
                vmg [(h0 + 1) * 256 + tt] = nvb - gp.y;
            }
        }
        __syncthreads();

        // stage 4: logits1 = lrelu(a @ Wa1 + ba1); thread -> (h=tt>>4, m-pair)
        // Wa1 layout [c][32] -> m-pairs are contiguous: packed loads, FFMA2.
        {
            const int h  = tt >> 4;
            const int m0 = (tt & 15) * 2;
            ull acc01 = pack2(ba1s[m0], ba1s[m0 + 1]);
            const float* arow = a_sh + h * 260;
            #pragma unroll 8
            for (int c = 0; c < 256; c += 4) {
                float4 av = *(const float4*)(arow + c);
                ull w0 = *(const ull*)(Wa1s + (c + 0) * 32 + m0);
                ull w1 = *(const ull*)(Wa1s + (c + 1) * 32 + m0);
                ull w2 = *(const ull*)(Wa1s + (c + 2) * 32 + m0);
                ull w3 = *(const ull*)(Wa1s + (c + 3) * 32 + m0);
                acc01 = ffma2(pack2(av.x, av.x), w0, acc01);
                acc01 = ffma2(pack2(av.y, av.y), w1, acc01);
                acc01 = ffma2(pack2(av.z, av.z), w2, acc01);
                acc01 = ffma2(pack2(av.w, av.w), w3, acc01);
            }
            float2 r = unpack2(acc01);
            l1s[h * 34 + m0    ] = lrelu(r.x);
            l1s[h * 34 + m0 + 1] = lrelu(r.y);
        }
        __syncthreads();

        // stage 5: logits2 = l1 @ Wa2 + ba2 (m-pairs packed)
        {
            const int h  = tt >> 4;
            const int m0 = (tt & 15) * 2;
            ull acc01 = pack2(ba2s[m0], ba2s[m0 + 1]);
            const float* lrow = l1s + h * 34;
            #pragma unroll
            for (int jj = 0; jj < 32; jj++) {
                const float lv = lrow[jj];
                ull w = *(const ull*)(Wa2s + jj * 32 + m0);
                acc01 = ffma2(pack2(lv, lv), w, acc01);
            }
            float2 r = unpack2(acc01);
            l2s[h * 34 + m0    ] = r.x;
            l2s[h * 34 + m0 + 1] = r.y;
        }
        __syncthreads();

        // stage 6: softmax over h (axis=1), one lane per m
        if (tt < 32) {
            float vals[16];
            float mx = -3.4e38f;
            #pragma unroll
            for (int h = 0; h < 16; h++) {
                vals[h] = l2s[h * 34 + tt];
                mx = fmaxf(mx, vals[h]);
            }
            float s = 0.f;
            #pragma unroll
            for (int h = 0; h < 16; h++) {
                vals[h] = __expf(vals[h] - mx);
                s += vals[h];
            }
            const float inv = 1.f / s;
            #pragma unroll
            for (int h = 0; h < 16; h++) attn[h * 34 + tt] = vals[h] * inv;
        }
        __syncthreads();

        // stage 7: out[c] = sum_h vmg[h][c] * attn[h][c>>3]
        {
            float acc = 0.f;
            const int mg = tt >> 3;
            #pragma unroll
            for (int h = 0; h < 16; h++)
                acc += vmg[h * 256 + tt] * attn[h * 34 + mg];
            if (do_store) out[n * 256 + tt] = acc;
        }
    }
}

// --------------------------- launch ------------------------------------------
extern "C" void kernel_launch(void* const* d_in, const int* in_sizes, int n_in,
                              void* d_out, int out_size) {
    const float* q_pts   = (const float*)d_in[0];
    const float* s_pts   = (const float*)d_in[1];
    const float* s_feats = (const float*)d_in[2];
    const void*  nb_inds = d_in[3];
    const float* Wq = (const float*)d_in[4];
    const float* bq = (const float*)d_in[5];
    const float* Wk = (const float*)d_in[6];
    const float* bk = (const float*)d_in[7];
    const float* Wv = (const float*)d_in[8];
    const float* bv = (const float*)d_in[9];
    const float* Wd1 = (const float*)d_in[10];
    const float* bd1 = (const float*)d_in[11];
    const float* Wd2 = (const float*)d_in[12];
    const float* bd2 = (const float*)d_in[13];
    const float* Wa1 = (const float*)d_in[14];
    const float* ba1 = (const float*)d_in[15];
    const float* Wa2 = (const float*)d_in[16];
    const float* ba2 = (const float*)d_in[17];
    float* out = (float*)d_out;

    const int N = in_sizes[0] / 3;

    cudaFuncSetAttribute(pt_fused_attn,
                         cudaFuncAttributeMaxDynamicSharedMemorySize, SMEM_BYTES);

    // 1) canonicalize indices (int64-or-int32 -> int32)
    pt_detect_idx<<<1, 256>>>((const unsigned*)nb_inds);
    pt_convert_idx<<<(N * HH + 255) / 256, 256>>>(nb_inds, N * HH);

    // 2) prepack concatenated QKV weights
    pt_prepack<<<(256 * 768 + 255) / 256, 256>>>(Wq, bq, Wk, bk, Wv, bv);

    // 3) QKV GEMM
    dim3 ggrid((N + 127) / 128, 6);
    pt_qkv_gemm<<<ggrid, 256>>>(s_feats, N);

    // 4) fused geometric attention (2 points per CTA iteration)
    int fgrid = 592;
    if (fgrid * 2 > N) fgrid = (N + 1) / 2;
    pt_fused_attn<<<fgrid, 512, SMEM_BYTES>>>(q_pts, s_pts,
                                              Wd1, bd1, Wd2, bd2,
                                              Wa1, ba1, Wa2, ba2,
                                              out, N);
}

// round 3
// speedup vs baseline: 1.6259x; 1.3456x over previous
#include <cuda_runtime.h>

// ---------------------------------------------------------------------------
// point_transformer fused kernel, Round 3
//   - Wa1 held in REGISTERS (32/thread, persistent) -> stage-4 smem traffic
//     drops ~30x (was the crossbar bottleneck)
//   - a / vmg / attn packed as h-pairs (f32x2), broadcast LDS reads
//   - nk/nv gathers prefetched into regs, hidden behind geom FMAs
// ---------------------------------------------------------------------------
#define NMAX 50000
#define HH   16

typedef unsigned long long ull;

__device__ float g_qkv[NMAX * 768];     // [n][0:256)=q [256:512)=k [512:768)=v
__device__ int   g_inds[NMAX * HH];
__device__ int   g_is32;
__device__ float g_wcat[256 * 768];
__device__ float g_bcat[768];

static __device__ __forceinline__ float lrelu(float x) {
    return fmaxf(x, 0.1f * x);
}
static __device__ __forceinline__ ull ffma2(ull a, ull b, ull c) {
    ull d;
    asm("fma.rn.f32x2 %0, %1, %2, %3;" : "=l"(d) : "l"(a), "l"(b), "l"(c));
    return d;
}
static __device__ __forceinline__ ull addf2(ull a, ull b) {
    ull d;
    asm("add.rn.f32x2 %0, %1, %2;" : "=l"(d) : "l"(a), "l"(b));
    return d;
}
static __device__ __forceinline__ ull pack2(float x, float y) {
    ull r;
    asm("mov.b64 %0, {%1, %2};" : "=l"(r) : "f"(x), "f"(y));
    return r;
}
static __device__ __forceinline__ float2 unpack2(ull v) {
    float2 f;
    asm("mov.b64 {%0, %1}, %2;" : "=f"(f.x), "=f"(f.y) : "l"(v));
    return f;
}

// --------------------------- index dtype handling ---------------------------
__global__ void pt_detect_idx(const unsigned* __restrict__ w) {
    __shared__ int flag;
    if (threadIdx.x == 0) flag = 0;
    __syncthreads();
    unsigned v = w[2 * threadIdx.x + 1];   // int64: odd words are zero
    if (v != 0u) flag = 1;
    __syncthreads();
    if (threadIdx.x == 0) g_is32 = flag;
}

__global__ void pt_convert_idx(const void* __restrict__ p, int total) {
    int i = blockIdx.x * blockDim.x + threadIdx.x;
    if (i >= total) return;
    if (g_is32) g_inds[i] = ((const int*)p)[i];
    else        g_inds[i] = (int)(((const long long*)p)[i]);
}

// --------------------------- weight prepack --------------------------------
__global__ void pt_prepack(const float* __restrict__ Wq, const float* __restrict__ bq,
                           const float* __restrict__ Wk, const float* __restrict__ bk,
                           const float* __restrict__ Wv, const float* __restrict__ bv) {
    int i = blockIdx.x * blockDim.x + threadIdx.x;
    if (i < 256 * 768) {
        int ci = i / 768, co = i % 768;
        float v;
        if      (co < 256) v = Wq[ci * 256 + co];
        else if (co < 512) v = Wk[ci * 256 + (co - 256)];
        else               v = Wv[ci * 256 + (co - 512)];
        g_wcat[i] = v;
    }
    if (i < 768) {
        g_bcat[i] = (i < 256) ? bq[i] : (i < 512 ? bk[i - 256] : bv[i - 512]);
    }
}

// --------------------------- QKV GEMM ---------------------------------------
__global__ void __launch_bounds__(256, 2)
pt_qkv_gemm(const float* __restrict__ A, int M) {
    __shared__ float As[2][16][128];
    __shared__ float Bs[2][16][128];

    const int t  = threadIdx.x;
    const int m0 = blockIdx.x * 128;
    const int n0 = blockIdx.y * 128;
    const int tx = t & 15;
    const int ty = t >> 4;

    const int ar = t >> 2;
    const int ac = (t & 3) * 4;
    const int br = t >> 5;
    const int bc = (t & 31) * 4;

    float4 a0, a1, b0, b1;
    {
        const int k0 = 0;
        a0 = (m0 + ar      < M) ? *(const float4*)&A[(m0 + ar     ) * 256 + k0 + ac] : make_float4(0.f,0.f,0.f,0.f);
        a1 = (m0 + ar + 64 < M) ? *(const float4*)&A[(m0 + ar + 64) * 256 + k0 + ac] : make_float4(0.f,0.f,0.f,0.f);
        b0 = *(const float4*)&g_wcat[(k0 + br    ) * 768 + n0 + bc];
        b1 = *(const float4*)&g_wcat[(k0 + br + 8) * 768 + n0 + bc];
        As[0][ac+0][ar] = a0.x; As[0][ac+1][ar] = a0.y; As[0][ac+2][ar] = a0.z; As[0][ac+3][ar] = a0.w;
        As[0][ac+0][ar+64] = a1.x; As[0][ac+1][ar+64] = a1.y; As[0][ac+2][ar+64] = a1.z; As[0][ac+3][ar+64] = a1.w;
        *(float4*)&Bs[0][br    ][bc] = b0;
        *(float4*)&Bs[0][br + 8][bc] = b1;
    }
    __syncthreads();

    ull acc2[8][4];
    #pragma unroll
    for (int i = 0; i < 8; i++)
        #pragma unroll
        for (int j = 0; j < 4; j++) acc2[i][j] = 0ull;

    for (int kt = 0; kt < 16; kt++) {
        const int cur = kt & 1;
        if (kt < 15) {
            const int k0 = (kt + 1) * 16;
            a0 = (m0 + ar      < M) ? *(const float4*)&A[(m0 + ar     ) * 256 + k0 + ac] : make_float4(0.f,0.f,0.f,0.f);
            a1 = (m0 + ar + 64 < M) ? *(const float4*)&A[(m0 + ar + 64) * 256 + k0 + ac] : make_float4(0.f,0.f,0.f,0.f);
            b0 = *(const float4*)&g_wcat[(k0 + br    ) * 768 + n0 + bc];
            b1 = *(const float4*)&g_wcat[(k0 + br + 8) * 768 + n0 + bc];
        }
        #pragma unroll
        for (int kk = 0; kk < 16; kk++) {
            float4 av0 = *(const float4*)&As[cur][kk][ty * 8];
            float4 av1 = *(const float4*)&As[cur][kk][ty * 8 + 4];
            ulonglong2 bq0 = *(const ulonglong2*)&Bs[cur][kk][tx * 8];
            ulonglong2 bq1 = *(const ulonglong2*)&Bs[cur][kk][tx * 8 + 4];
            ull bp[4] = {bq0.x, bq0.y, bq1.x, bq1.y};
            float av[8] = {av0.x, av0.y, av0.z, av0.w, av1.x, av1.y, av1.z, av1.w};
            #pragma unroll
            for (int i = 0; i < 8; i++) {
                ull ai = pack2(av[i], av[i]);
                #pragma unroll
                for (int j = 0; j < 4; j++)
                    acc2[i][j] = ffma2(ai, bp[j], acc2[i][j]);
            }
        }
        if (kt < 15) {
            const int nxt = cur ^ 1;
            As[nxt][ac+0][ar] = a0.x; As[nxt][ac+1][ar] = a0.y; As[nxt][ac+2][ar] = a0.z; As[nxt][ac+3][ar] = a0.w;
            As[nxt][ac+0][ar+64] = a1.x; As[nxt][ac+1][ar+64] = a1.y; As[nxt][ac+2][ar+64] = a1.z; As[nxt][ac+3][ar+64] = a1.w;
            *(float4*)&Bs[nxt][br    ][bc] = b0;
            *(float4*)&Bs[nxt][br + 8][bc] = b1;
        }
        __syncthreads();
    }

    float4 bb0 = *(const float4*)&g_bcat[n0 + tx * 8];
    float4 bb1 = *(const float4*)&g_bcat[n0 + tx * 8 + 4];
    #pragma unroll
    for (int i = 0; i < 8; i++) {
        int row = m0 + ty * 8 + i;
        if (row < M) {
            float2 c0 = unpack2(acc2[i][0]);
            float2 c1 = unpack2(acc2[i][1]);
            float2 c2 = unpack2(acc2[i][2]);
            float2 c3 = unpack2(acc2[i][3]);
            float4 o0 = make_float4(c0.x + bb0.x, c0.y + bb0.y, c1.x + bb0.z, c1.y + bb0.w);
            float4 o1 = make_float4(c2.x + bb1.x, c2.y + bb1.y, c3.x + bb1.z, c3.y + bb1.w);
            *(float4*)&g_qkv[row * 768 + n0 + tx * 8    ] = o0;
            *(float4*)&g_qkv[row * 768 + n0 + tx * 8 + 4] = o1;
        }
    }
}

// --------------------------- fused attention --------------------------------
// 512 threads = two 256-thread halves, one point each per iteration.
// Weight region (floats):
#define OFF_WD2   0        // [64][256]
#define OFF_WA2   16384    // [32][32]
#define OFF_WD1   17408    // [3][64]
#define OFF_BD1   17600    // 64
#define OFF_BD2   17664    // 256
#define OFF_BA1   17920    // 32
#define OFF_BA2   17952    // 32
#define WEIGHT_FLOATS 17984

// per-point block offsets (floats, relative)
#define PP_HID    0        // [64][16]
#define PP_A2     1024     // ull [8][258]  (a, packed h-pairs)
#define PP_VMG    5152     // ull [8][258]  (v - geom, packed h-pairs)
#define PP_PART   9280     // ull [8 ww][8 hp][32 m] stage-4 partials
#define PP_L1     13376    // [16][34]
#define PP_L2     13920    // [16][34]
#define PP_ATTN   14464    // ull [8][34]
#define PP_INDS   15008    // 16 ints
#define PP_QPT    15024    // 3 floats + pad
#define PP_FLOATS 15040

#define SMEM_FLOATS (WEIGHT_FLOATS + 2 * PP_FLOATS)
#define SMEM_BYTES  (SMEM_FLOATS * 4)

__global__ void __launch_bounds__(512, 1)
pt_fused_attn(const float* __restrict__ q_pts,
              const float* __restrict__ s_pts,
              const float* __restrict__ Wd1, const float* __restrict__ bd1,
              const float* __restrict__ Wd2, const float* __restrict__ bd2,
              const float* __restrict__ Wa1, const float* __restrict__ ba1,
              const float* __restrict__ Wa2, const float* __restrict__ ba2,
              float* __restrict__ out, int N) {
    extern __shared__ float sm[];
    float* Wd2s = sm + OFF_WD2;
    float* Wa2s = sm + OFF_WA2;
    float* Wd1s = sm + OFF_WD1;
    float* bd1s = sm + OFF_BD1;
    float* bd2s = sm + OFF_BD2;
    float* ba1s = sm + OFF_BA1;
    float* ba2s = sm + OFF_BA2;

    const int t   = threadIdx.x;
    const int pid = t >> 8;        // point half
    const int tt  = t & 255;       // thread (channel c) within half
    const int ww  = (t >> 5) & 7;  // warp within half: owns c-slice [32ww,32ww+32)
    const int l   = t & 31;        // lane: owns output column m = l

    float* pp     = sm + WEIGHT_FLOATS + pid * PP_FLOATS;
    float* hid    = pp + PP_HID;
    ull*   a2u    = (ull*)(pp + PP_A2);     // [8 hp][258 c]
    ull*   vmg2   = (ull*)(pp + PP_VMG);    // [8 hp][258 c]
    ull*   partu  = (ull*)(pp + PP_PART);   // [(ww*8+hp)*32 + m]
    float* l1s    = pp + PP_L1;
    float* l2s    = pp + PP_L2;
    ull*   attn2  = (ull*)(pp + PP_ATTN);   // [8 hp][34 m]
    int*   inds_s = (int*)(pp + PP_INDS);
    float* qptf   = pp + PP_QPT;

    // persistent Wa1 register cache: wreg[j] = Wa1[32*ww + j][l]
    float wreg[32];
    #pragma unroll
    for (int j = 0; j < 32; j++)
        wreg[j] = Wa1[(ww * 32 + j) * 32 + l];

    // stage 0: remaining weights -> shared (once per CTA)
    for (int i = t; i < 16384; i += 512) Wd2s[i] = Wd2[i];
    for (int i = t; i < 1024;  i += 512) Wa2s[i] = Wa2[i];
    if (t < 192) Wd1s[t] = Wd1[t];
    if (t < 64)  bd1s[t] = bd1[t];
    if (t < 256) bd2s[t] = bd2[t];
    if (t < 32) { ba1s[t] = ba1[t]; ba2s[t] = ba2[t]; }
    __syncthreads();

    for (int n2 = blockIdx.x; n2 * 2 < N; n2 += gridDim.x) {
        const int nreq = n2 * 2 + pid;
        const int n = (nreq < N) ? nreq : (N - 1);
        const bool do_store = (nreq < N);

        __syncthreads();   // previous iteration's smem readers done
        if (tt < 16) inds_s[tt] = g_inds[n * 16 + tt];
        if (tt < 3)  qptf[tt]   = q_pts[n * 3 + tt];
        __syncthreads();

        // prefetch gathers (L2 latency hidden behind stage 1+2 math)
        float nk[16], nv[16];
        const float qf = g_qkv[inds_s[0] * 768 + tt];
        #pragma unroll
        for (int h = 0; h < 16; h++) {
            const int j = inds_s[h];
            nk[h] = g_qkv[j * 768 + 256 + tt];
            nv[h] = g_qkv[j * 768 + 512 + tt];
        }

        // stage 1: hidden[64][16] = lrelu(rel @ Wd1 + bd1), stored [d][h]
        {
            const int h  = tt >> 4;
            const int d0 = (tt & 15) << 2;
            const int j  = inds_s[h];
            const float rx = s_pts[j * 3 + 0] - qptf[0];
            const float ry = s_pts[j * 3 + 1] - qptf[1];
            const float rz = s_pts[j * 3 + 2] - qptf[2];
            #pragma unroll
            for (int i = 0; i < 4; i++) {
                const int d = d0 + i;
                float v = rx * Wd1s[d] + ry * Wd1s[64 + d] + rz * Wd1s[128 + d] + bd1s[d];
                hid[d * 16 + h] = lrelu(v);
            }
        }
        __syncthreads();

        // stage 2: geom[h][c=tt] as 8 packed h-pairs
        ull g[8];
        {
            const float b2 = bd2s[tt];
            const ull b2p = pack2(b2, b2);
            #pragma unroll
            for (int hp = 0; hp < 8; hp++) g[hp] = b2p;
            #pragma unroll 4
            for (int d = 0; d < 64; d++) {
                const float w = Wd2s[d * 256 + tt];
                const ull ww2 = pack2(w, w);
                const ulonglong2* hp4 = (const ulonglong2*)(hid + d * 16);
                ulonglong2 h01 = hp4[0], h23 = hp4[1], h45 = hp4[2], h67 = hp4[3];
                g[0] = ffma2(ww2, h01.x, g[0]);
                g[1] = ffma2(ww2, h01.y, g[1]);
                g[2] = ffma2(ww2, h23.x, g[2]);
                g[3] = ffma2(ww2, h23.y, g[3]);
                g[4] = ffma2(ww2, h45.x, g[4]);
                g[5] = ffma2(ww2, h45.y, g[5]);
                g[6] = ffma2(ww2, h67.x, g[6]);
                g[7] = ffma2(ww2, h67.y, g[7]);
            }
        }

        // stage 3: a = lrelu(qf - nk - geom), vmg = nv - geom (packed h-pairs)
        #pragma unroll
        for (int hp = 0; hp < 8; hp++) {
            const float2 gp = unpack2(g[hp]);
            const float ax = lrelu(qf - nk[2*hp]     - gp.x);
            const float ay = lrelu(qf - nk[2*hp + 1] - gp.y);
            a2u [hp * 258 + tt] = pack2(ax, ay);
            vmg2[hp * 258 + tt] = pack2(nv[2*hp] - gp.x, nv[2*hp + 1] - gp.y);
        }
        __syncthreads();

        // stage 4: partial[ww][h][m=l] = sum_{c in slice} a[h][c] * Wa1[c][m]
        // a from broadcast LDS.128, Wa1 from registers.
        {
            ull acc[8];
            #pragma unroll
            for (int hp = 0; hp < 8; hp++) acc[hp] = 0ull;
            const int cbase = ww * 32;
            #pragma unroll
            for (int jv = 0; jv < 16; jv++) {
                const ull w0 = pack2(wreg[2*jv],     wreg[2*jv]);
                const ull w1 = pack2(wreg[2*jv + 1], wreg[2*jv + 1]);
                #pragma unroll
                for (int hp = 0; hp < 8; hp++) {
                    ulonglong2 av = *(const ulonglong2*)&a2u[hp * 258 + cbase + 2*jv];
                    acc[hp] = ffma2(av.x, w0, acc[hp]);
                    acc[hp] = ffma2(av.y, w1, acc[hp]);
                }
            }
            #pragma unroll
            for (int hp = 0; hp < 8; hp++)
                partu[(ww * 8 + hp) * 32 + l] = acc[hp];
        }
        __syncthreads();

        // stage 4b: reduce 8 warp-partials, add bias, lrelu -> l1s[16][34]
        {
            const int hp = tt >> 5;
            const int m  = tt & 31;
            const float b = ba1s[m];
            ull s = pack2(b, b);
            #pragma unroll
            for (int w8 = 0; w8 < 8; w8++)
                s = addf2(s, partu[(w8 * 8 + hp) * 32 + m]);
            float2 v = unpack2(s);
            l1s[(2*hp    ) * 34 + m] = lrelu(v.x);
            l1s[(2*hp + 1) * 34 + m] = lrelu(v.y);
        }
        __syncthreads();

        // stage 5: logits2 = l1 @ Wa2 + ba2 (m-pairs packed)
        {
            const int h  = tt >> 4;
            const int m0 = (tt & 15) * 2;
            ull acc01 = pack2(ba2s[m0], ba2s[m0 + 1]);
            const float* lrow = l1s + h * 34;
            #pragma unroll
            for (int jj = 0; jj < 32; jj++) {
                const float lv = lrow[jj];
                ull w = *(const ull*)(Wa2s + jj * 32 + m0);
                acc01 = ffma2(pack2(lv, lv), w, acc01);
            }
            float2 r = unpack2(acc01);
            l2s[h * 34 + m0    ] = r.x;
            l2s[h * 34 + m0 + 1] = r.y;
        }
        __syncthreads();

        // stage 6: softmax over h, one lane per m; write packed h-pairs
        if (tt < 32) {
            float vals[16];
            float mx = -3.4e38f;
            #pragma unroll
            for (int h = 0; h < 16; h++) {
                vals[h] = l2s[h * 34 + tt];
                mx = fmaxf(mx, vals[h]);
            }
            float s = 0.f;
            #pragma unroll
            for (int h = 0; h < 16; h++) {
                vals[h] = __expf(vals[h] - mx);
                s += vals[h];
            }
            const float inv = 1.f / s;
            #pragma unroll
            for (int hp = 0; hp < 8; hp++)
                attn2[hp * 34 + tt] = pack2(vals[2*hp] * inv, vals[2*hp + 1] * inv);
        }
        __syncthreads();

        // stage 7: out[c] = sum_h vmg[h][c] * attn[h][c>>3]  (packed h-pairs)
        {
            const int mg = tt >> 3;
            ull acc2p = 0ull;
            #pragma unroll
            for (int hp = 0; hp < 8; hp++)
                acc2p = ffma2(vmg2[hp * 258 + tt], attn2[hp * 34 + mg], acc2p);
            float2 r = unpack2(acc2p);
            if (do_store) out[n * 256 + tt] = r.x + r.y;
        }
    }
}

// --------------------------- launch ------------------------------------------
extern "C" void kernel_launch(void* const* d_in, const int* in_sizes, int n_in,
                              void* d_out, int out_size) {
    const float* q_pts   = (const float*)d_in[0];
    const float* s_pts   = (const float*)d_in[1];
    const float* s_feats = (const float*)d_in[2];
    const void*  nb_inds = d_in[3];
    const float* Wq = (const float*)d_in[4];
    const float* bq = (const float*)d_in[5];
    const float* Wk = (const float*)d_in[6];
    const float* bk = (const float*)d_in[7];
    const float* Wv = (const float*)d_in[8];
    const float* bv = (const float*)d_in[9];
    const float* Wd1 = (const float*)d_in[10];
    const float* bd1 = (const float*)d_in[11];
    const float* Wd2 = (const float*)d_in[12];
    const float* bd2 = (const float*)d_in[13];
    const float* Wa1 = (const float*)d_in[14];
    const float* ba1 = (const float*)d_in[15];
    const float* Wa2 = (const float*)d_in[16];
    const float* ba2 = (const float*)d_in[17];
    float* out = (float*)d_out;

    const int N = in_sizes[0] / 3;

    cudaFuncSetAttribute(pt_fused_attn,
                         cudaFuncAttributeMaxDynamicSharedMemorySize, SMEM_BYTES);

    pt_detect_idx<<<1, 256>>>((const unsigned*)nb_inds);
    pt_convert_idx<<<(N * HH + 255) / 256, 256>>>(nb_inds, N * HH);
    pt_prepack<<<(256 * 768 + 255) / 256, 256>>>(Wq, bq, Wk, bk, Wv, bv);

    dim3 ggrid((N + 127) / 128, 6);
    pt_qkv_gemm<<<ggrid, 256>>>(s_feats, N);

    int fgrid = 148;
    if (fgrid * 2 > N) fgrid = (N + 1) / 2;
    pt_fused_attn<<<fgrid, 512, SMEM_BYTES>>>(q_pts, s_pts,
                                              Wd1, bd1, Wd2, bd2,
                                              Wa1, ba1, Wa2, ba2,
                                              out, N);
}

// round 5
// speedup vs baseline: 1.8370x; 1.1298x over previous
#include <cuda_runtime.h>
#include <cuda_bf16.h>

// ---------------------------------------------------------------------------
// point_transformer, Round 5
//   - QKV GEMM via mma.sync m16n8k16 bf16 (hi/lo split, fp32 accum)
//     [tcgen05 unavailable: harness ptxas target is sm_103 without 'a' feature]
//   - fused attention: per-half named barriers, vmg kept in registers
// ---------------------------------------------------------------------------
#define NMAX 50000
#define MPAD 50048     // 391 * 128
#define HH   16

typedef unsigned long long ull;

__device__ float g_qkv[NMAX * 768];     // [n][0:256)=q [256:512)=k [512:768)=v
__device__ int   g_inds[NMAX * HH];
__device__ int   g_is32;
__device__ float g_bcat[768];
__device__ __nv_bfloat16 g_ahi[MPAD * 256];
__device__ __nv_bfloat16 g_alo[MPAD * 256];
__device__ __nv_bfloat16 g_whiT[768 * 256];   // Wcat^T: [n][k]
__device__ __nv_bfloat16 g_wloT[768 * 256];

static __device__ __forceinline__ float lrelu(float x) {
    return fmaxf(x, 0.1f * x);
}
static __device__ __forceinline__ ull ffma2(ull a, ull b, ull c) {
    ull d;
    asm("fma.rn.f32x2 %0, %1, %2, %3;" : "=l"(d) : "l"(a), "l"(b), "l"(c));
    return d;
}
static __device__ __forceinline__ ull addf2(ull a, ull b) {
    ull d;
    asm("add.rn.f32x2 %0, %1, %2;" : "=l"(d) : "l"(a), "l"(b));
    return d;
}
static __device__ __forceinline__ ull pack2(float x, float y) {
    ull r;
    asm("mov.b64 %0, {%1, %2};" : "=l"(r) : "f"(x), "f"(y));
    return r;
}
static __device__ __forceinline__ float2 unpack2(ull v) {
    float2 f;
    asm("mov.b64 {%0, %1}, %2;" : "=f"(f.x), "=f"(f.y) : "l"(v));
    return f;
}
static __device__ __forceinline__ void mma_bf16(float* d, const unsigned* a,
                                                const unsigned* b) {
    asm volatile(
        "mma.sync.aligned.m16n8k16.row.col.f32.bf16.bf16.f32 "
        "{%0,%1,%2,%3}, {%4,%5,%6,%7}, {%8,%9}, {%0,%1,%2,%3};"
        : "+f"(d[0]), "+f"(d[1]), "+f"(d[2]), "+f"(d[3])
        : "r"(a[0]), "r"(a[1]), "r"(a[2]), "r"(a[3]), "r"(b[0]), "r"(b[1]));
}

// --------------------------- index dtype handling ---------------------------
__global__ void pt_detect_idx(const unsigned* __restrict__ w) {
    __shared__ int flag;
    if (threadIdx.x == 0) flag = 0;
    __syncthreads();
    unsigned v = w[2 * threadIdx.x + 1];   // int64: odd words are zero
    if (v != 0u) flag = 1;
    __syncthreads();
    if (threadIdx.x == 0) g_is32 = flag;
}

__global__ void pt_convert_idx(const void* __restrict__ p, int total) {
    int i = blockIdx.x * blockDim.x + threadIdx.x;
    if (i >= total) return;
    if (g_is32) g_inds[i] = ((const int*)p)[i];
    else        g_inds[i] = (int)(((const long long*)p)[i]);
}

// --------------------------- prepacks ---------------------------------------
__global__ void pt_prepack_w(const float* __restrict__ Wq, const float* __restrict__ bq,
                             const float* __restrict__ Wk, const float* __restrict__ bk,
                             const float* __restrict__ Wv, const float* __restrict__ bv) {
    int i = blockIdx.x * blockDim.x + threadIdx.x;
    if (i < 768 * 256) {
        int n = i >> 8, k = i & 255;
        float w;
        if      (n < 256) w = Wq[k * 256 + n];
        else if (n < 512) w = Wk[k * 256 + (n - 256)];
        else              w = Wv[k * 256 + (n - 512)];
        __nv_bfloat16 hi = __float2bfloat16(w);
        float lo = w - __bfloat162float(hi);
        g_whiT[i] = hi;
        g_wloT[i] = __float2bfloat16(lo);
    }
    if (i < 768) {
        g_bcat[i] = (i < 256) ? bq[i] : (i < 512 ? bk[i - 256] : bv[i - 512]);
    }
}

__global__ void pt_cvt_a(const float* __restrict__ A, int M) {
    int i = blockIdx.x * blockDim.x + threadIdx.x;
    if (i >= MPAD * 256) return;
    int row = i >> 8;
    float a = (row < M) ? A[i] : 0.f;
    __nv_bfloat16 hi = __float2bfloat16(a);
    float lo = a - __bfloat162float(hi);
    g_ahi[i] = hi;
    g_alo[i] = __float2bfloat16(lo);
}

// --------------------------- mma.sync QKV GEMM ------------------------------
// C[128m x 128n] per CTA; K=256 in 8 chunks of 32; warp grid 2m x 4n.
// smem k-stride 40 bf16: 16B-aligned uint4 fills AND conflict-free frag LDS.
#define SK 40

__global__ void __launch_bounds__(256, 2)
pt_qkv_gemm_mma(int M) {
    __shared__ __align__(16) __nv_bfloat16 smAhi[128 * SK];
    __shared__ __align__(16) __nv_bfloat16 smAlo[128 * SK];
    __shared__ __align__(16) __nv_bfloat16 smBhi[128 * SK];
    __shared__ __align__(16) __nv_bfloat16 smBlo[128 * SK];

    const int t    = threadIdx.x;
    const int warp = t >> 5;
    const int lane = t & 31;
    const int gid  = lane >> 2;     // 0..7
    const int tq   = lane & 3;      // 0..3
    const int m0 = blockIdx.x * 128;
    const int n0 = blockIdx.y * 128;
    const int mw = (warp & 1) * 64;     // warp m-offset
    const int nw = (warp >> 1) * 32;    // warp n-offset

    float acc[4][4][4];
    #pragma unroll
    for (int mt = 0; mt < 4; mt++)
        #pragma unroll
        for (int nt = 0; nt < 4; nt++)
            #pragma unroll
            for (int r = 0; r < 4; r++) acc[mt][nt][r] = 0.f;

    for (int kc = 0; kc < 8; kc++) {
        const int k0 = kc * 32;
        __syncthreads();
        #pragma unroll
        for (int u = 0; u < 2; u++) {
            int q   = t + u * 256;      // 0..511 uint4 slots (128 rows x 4)
            int row = q >> 2;
            int kq  = q & 3;
            int dst = row * SK + kq * 8;
            int asrc = (m0 + row) * 256 + k0 + kq * 8;
            int bsrc = (n0 + row) * 256 + k0 + kq * 8;
            *(uint4*)&smAhi[dst] = *(const uint4*)&g_ahi[asrc];
            *(uint4*)&smAlo[dst] = *(const uint4*)&g_alo[asrc];
            *(uint4*)&smBhi[dst] = *(const uint4*)&g_whiT[bsrc];
            *(uint4*)&smBlo[dst] = *(const uint4*)&g_wloT[bsrc];
        }
        __syncthreads();

        #pragma unroll
        for (int ks = 0; ks < 2; ks++) {
            const int kk = ks * 16 + tq * 2;
            unsigned bh[4][2], bl[4][2];
            #pragma unroll
            for (int nt = 0; nt < 4; nt++) {
                const int nr = nw + nt * 8 + gid;
                bh[nt][0] = *(const unsigned*)&smBhi[nr * SK + kk];
                bh[nt][1] = *(const unsigned*)&smBhi[nr * SK + kk + 8];
                bl[nt][0] = *(const unsigned*)&smBlo[nr * SK + kk];
                bl[nt][1] = *(const unsigned*)&smBlo[nr * SK + kk + 8];
            }
            #pragma unroll
            for (int mt = 0; mt < 4; mt++) {
                const int mr = mw + mt * 16 + gid;
                unsigned ah[4], al[4];
                ah[0] = *(const unsigned*)&smAhi[ mr      * SK + kk];
                ah[1] = *(const unsigned*)&smAhi[(mr + 8) * SK + kk];
                ah[2] = *(const unsigned*)&smAhi[ mr      * SK + kk + 8];
                ah[3] = *(const unsigned*)&smAhi[(mr + 8) * SK + kk + 8];
                al[0] = *(const unsigned*)&smAlo[ mr      * SK + kk];
                al[1] = *(const unsigned*)&smAlo[(mr + 8) * SK + kk];
                al[2] = *(const unsigned*)&smAlo[ mr      * SK + kk + 8];
                al[3] = *(const unsigned*)&smAlo[(mr + 8) * SK + kk + 8];
                #pragma unroll
                for (int nt = 0; nt < 4; nt++) {
                    mma_bf16(acc[mt][nt], ah, bh[nt]);   // hi*hi
                    mma_bf16(acc[mt][nt], ah, bl[nt]);   // hi*lo
                    mma_bf16(acc[mt][nt], al, bh[nt]);   // lo*hi
                }
            }
        }
    }

    // epilogue: +bias, store (float2 per row-half per tile)
    #pragma unroll
    for (int mt = 0; mt < 4; mt++) {
        const int r0 = m0 + mw + mt * 16 + gid;
        const int r1 = r0 + 8;
        #pragma unroll
        for (int nt = 0; nt < 4; nt++) {
            const int col = n0 + nw + nt * 8 + tq * 2;
            const float b0 = g_bcat[col], b1 = g_bcat[col + 1];
            if (r0 < M) {
                float2 o = make_float2(acc[mt][nt][0] + b0, acc[mt][nt][1] + b1);
                *(float2*)&g_qkv[r0 * 768 + col] = o;
            }
            if (r1 < M) {
                float2 o = make_float2(acc[mt][nt][2] + b0, acc[mt][nt][3] + b1);
                *(float2*)&g_qkv[r1 * 768 + col] = o;
            }
        }
    }
}

// --------------------------- fused attention --------------------------------
// 512 threads = two independent 256-thread halves (named barriers 1/2).
#define OFF_WD2   0        // [64][256]
#define OFF_WA2   16384    // [32][32]
#define OFF_WD1   17408    // [3][64]
#define OFF_BD1   17600
#define OFF_BD2   17664
#define OFF_BA1   17920
#define OFF_BA2   17952
#define WEIGHT_FLOATS 17984

#define PP_HID    0        // [64][16]
#define PP_A2     1024     // ull [8][258]
#define PP_PART   5152     // ull [8 ww][8 hp][32 m]
#define PP_L1     9248     // [16][34]
#define PP_L2     9792     // [16][34]
#define PP_ATTN   10336    // ull [8][34]
#define PP_INDS   10880    // 16 ints
#define PP_QPT    10896    // 3 floats + pad
#define PP_FLOATS 10912

#define SMEM_FLOATS (WEIGHT_FLOATS + 2 * PP_FLOATS)
#define SMEM_BYTES  (SMEM_FLOATS * 4)

#define HBAR(id) asm volatile("bar.sync %0, 256;" :: "r"(id) : "memory")

extern __shared__ float sm_dyn[];

__global__ void __launch_bounds__(512, 1)
pt_fused_attn(const float* __restrict__ q_pts,
              const float* __restrict__ s_pts,
              const float* __restrict__ Wd1, const float* __restrict__ bd1,
              const float* __restrict__ Wd2, const float* __restrict__ bd2,
              const float* __restrict__ Wa1, const float* __restrict__ ba1,
              const float* __restrict__ Wa2, const float* __restrict__ ba2,
              float* __restrict__ out, int N) {
    float* sm = sm_dyn;
    float* Wd2s = sm + OFF_WD2;
    float* Wa2s = sm + OFF_WA2;
    float* Wd1s = sm + OFF_WD1;
    float* bd1s = sm + OFF_BD1;
    float* bd2s = sm + OFF_BD2;
    float* ba1s = sm + OFF_BA1;
    float* ba2s = sm + OFF_BA2;

    const int t   = threadIdx.x;
    const int pid = t >> 8;
    const int tt  = t & 255;
    const int ww  = (t >> 5) & 7;
    const int l   = t & 31;
    const int bid = pid + 1;       // named barrier id for this half

    float* pp     = sm + WEIGHT_FLOATS + pid * PP_FLOATS;
    float* hid    = pp + PP_HID;
    ull*   a2u    = (ull*)(pp + PP_A2);
    ull*   partu  = (ull*)(pp + PP_PART);
    float* l1s    = pp + PP_L1;
    float* l2s    = pp + PP_L2;
    ull*   attn2  = (ull*)(pp + PP_ATTN);
    int*   inds_s = (int*)(pp + PP_INDS);
    float* qptf   = pp + PP_QPT;

    // persistent Wa1 register cache: wreg[j] = Wa1[32*ww + j][l]
    float wreg[32];
    #pragma unroll
    for (int j = 0; j < 32; j++)
        wreg[j] = Wa1[(ww * 32 + j) * 32 + l];

    for (int i = t; i < 16384; i += 512) Wd2s[i] = Wd2[i];
    for (int i = t; i < 1024;  i += 512) Wa2s[i] = Wa2[i];
    if (t < 192) Wd1s[t] = Wd1[t];
    if (t < 64)  bd1s[t] = bd1[t];
    if (t < 256) bd2s[t] = bd2[t];
    if (t < 32) { ba1s[t] = ba1[t]; ba2s[t] = ba2[t]; }
    __syncthreads();

    for (int n2 = blockIdx.x; n2 * 2 < N; n2 += gridDim.x) {
        const int nreq = n2 * 2 + pid;
        const int n = (nreq < N) ? nreq : (N - 1);
        const bool do_store = (nreq < N);

        if (tt < 16) inds_s[tt] = g_inds[n * 16 + tt];
        if (tt < 3)  qptf[tt]   = q_pts[n * 3 + tt];
        HBAR(bid);

        // prefetch gathers (hidden behind stage 1+2 math)
        float nk[16], nv[16];
        const float qf = g_qkv[inds_s[0] * 768 + tt];
        #pragma unroll
        for (int h = 0; h < 16; h++) {
            const int j = inds_s[h];
            nk[h] = g_qkv[j * 768 + 256 + tt];
            nv[h] = g_qkv[j * 768 + 512 + tt];
        }

        // stage 1: hidden[64][16] = lrelu(rel @ Wd1 + bd1), stored [d][h]
        {
            const int h  = tt >> 4;
            const int d0 = (tt & 15) << 2;
            const int j  = inds_s[h];
            const float rx = s_pts[j * 3 + 0] - qptf[0];
            const float ry = s_pts[j * 3 + 1] - qptf[1];
            const float rz = s_pts[j * 3 + 2] - qptf[2];
            #pragma unroll
            for (int i = 0; i < 4; i++) {
                const int d = d0 + i;
                float v = rx * Wd1s[d] + ry * Wd1s[64 + d] + rz * Wd1s[128 + d] + bd1s[d];
                hid[d * 16 + h] = lrelu(v);
            }
        }
        HBAR(bid);

        // stage 2: geom[h][c=tt] as 8 packed h-pairs
        ull g[8];
        {
            const float b2 = bd2s[tt];
            const ull b2p = pack2(b2, b2);
            #pragma unroll
            for (int hp = 0; hp < 8; hp++) g[hp] = b2p;
            #pragma unroll 4
            for (int d = 0; d < 64; d++) {
                const float w = Wd2s[d * 256 + tt];
                const ull ww2 = pack2(w, w);
                const ulonglong2* hp4 = (const ulonglong2*)(hid + d * 16);
                ulonglong2 h01 = hp4[0], h23 = hp4[1], h45 = hp4[2], h67 = hp4[3];
                g[0] = ffma2(ww2, h01.x, g[0]);
                g[1] = ffma2(ww2, h01.y, g[1]);
                g[2] = ffma2(ww2, h23.x, g[2]);
                g[3] = ffma2(ww2, h23.y, g[3]);
                g[4] = ffma2(ww2, h45.x, g[4]);
                g[5] = ffma2(ww2, h45.y, g[5]);
                g[6] = ffma2(ww2, h67.x, g[6]);
                g[7] = ffma2(ww2, h67.y, g[7]);
            }
        }

        // stage 3: a = lrelu(qf - nk - geom) -> smem packed; vmg stays in regs
        #pragma unroll
        for (int hp = 0; hp < 8; hp++) {
            const float2 gp = unpack2(g[hp]);
            const float ax = lrelu(qf - nk[2*hp]     - gp.x);
            const float ay = lrelu(qf - nk[2*hp + 1] - gp.y);
            a2u[hp * 258 + tt] = pack2(ax, ay);
        }
        HBAR(bid);

        // stage 4: partial[ww][h][m=l] from register Wa1 + broadcast LDS.128
        {
            ull acc[8];
            #pragma unroll
            for (int hp = 0; hp < 8; hp++) acc[hp] = 0ull;
            const int cbase = ww * 32;
            #pragma unroll
            for (int jv = 0; jv < 16; jv++) {
                const ull w0 = pack2(wreg[2*jv],     wreg[2*jv]);
                const ull w1 = pack2(wreg[2*jv + 1], wreg[2*jv + 1]);
                #pragma unroll
                for (int hp = 0; hp < 8; hp++) {
                    ulonglong2 av = *(const ulonglong2*)&a2u[hp * 258 + cbase + 2*jv];
                    acc[hp] = ffma2(av.x, w0, acc[hp]);
                    acc[hp] = ffma2(av.y, w1, acc[hp]);
                }
            }
            #pragma unroll
            for (int hp = 0; hp < 8; hp++)
                partu[(ww * 8 + hp) * 32 + l] = acc[hp];
        }
        HBAR(bid);

        // stage 4b: reduce warp partials, bias, lrelu -> l1s
        {
            const int hp = tt >> 5;
            const int m  = tt & 31;
            const float b = ba1s[m];
            ull s = pack2(b, b);
            #pragma unroll
            for (int w8 = 0; w8 < 8; w8++)
                s = addf2(s, partu[(w8 * 8 + hp) * 32 + m]);
            float2 v = unpack2(s);
            l1s[(2*hp    ) * 34 + m] = lrelu(v.x);
            l1s[(2*hp + 1) * 34 + m] = lrelu(v.y);
        }
        HBAR(bid);

        // stage 5: logits2 = l1 @ Wa2 + ba2
        {
            const int h  = tt >> 4;
            const int m0 = (tt & 15) * 2;
            ull acc01 = pack2(ba2s[m0], ba2s[m0 + 1]);
            const float* lrow = l1s + h * 34;
            #pragma unroll
            for (int jj = 0; jj < 32; jj++) {
                const float lv = lrow[jj];
                ull w = *(const ull*)(Wa2s + jj * 32 + m0);
                acc01 = ffma2(pack2(lv, lv), w, acc01);
            }
            float2 r = unpack2(acc01);
            l2s[h * 34 + m0    ] = r.x;
            l2s[h * 34 + m0 + 1] = r.y;
        }
        HBAR(bid);

        // stage 6: softmax over h
        if (tt < 32) {
            float vals[16];
            float mx = -3.4e38f;
            #pragma unroll
            for (int h = 0; h < 16; h++) {
                vals[h] = l2s[h * 34 + tt];
                mx = fmaxf(mx, vals[h]);
            }
            float s = 0.f;
            #pragma unroll
            for (int h = 0; h < 16; h++) {
                vals[h] = __expf(vals[h] - mx);
                s += vals[h];
            }
            const float inv = 1.f / s;
            #pragma unroll
            for (int hp = 0; hp < 8; hp++)
                attn2[hp * 34 + tt] = pack2(vals[2*hp] * inv, vals[2*hp + 1] * inv);
        }
        HBAR(bid);

        // stage 7: out[c] = sum_h (nv[h]-geom[h]) * attn[h][c>>3]  (from regs)
        {
            const int mg = tt >> 3;
            ull acc2p = 0ull;
            #pragma unroll
            for (int hp = 0; hp < 8; hp++) {
                const float2 gp = unpack2(g[hp]);
                ull vm = pack2(nv[2*hp] - gp.x, nv[2*hp + 1] - gp.y);
                acc2p = ffma2(vm, attn2[hp * 34 + mg], acc2p);
            }
            float2 r = unpack2(acc2p);
            if (do_store) out[n * 256 + tt] = r.x + r.y;
        }
    }
}

// --------------------------- launch ------------------------------------------
extern "C" void kernel_launch(void* const* d_in, const int* in_sizes, int n_in,
                              void* d_out, int out_size) {
    const float* q_pts   = (const float*)d_in[0];
    const float* s_pts   = (const float*)d_in[1];
    const float* s_feats = (const float*)d_in[2];
    const void*  nb_inds = d_in[3];
    const float* Wq = (const float*)d_in[4];
    const float* bq = (const float*)d_in[5];
    const float* Wk = (const float*)d_in[6];
    const float* bk = (const float*)d_in[7];
    const float* Wv = (const float*)d_in[8];
    const float* bv = (const float*)d_in[9];
    const float* Wd1 = (const float*)d_in[10];
    const float* bd1 = (const float*)d_in[11];
    const float* Wd2 = (const float*)d_in[12];
    const float* bd2 = (const float*)d_in[13];
    const float* Wa1 = (const float*)d_in[14];
    const float* ba1 = (const float*)d_in[15];
    const float* Wa2 = (const float*)d_in[16];
    const float* ba2 = (const float*)d_in[17];
    float* out = (float*)d_out;

    const int N = in_sizes[0] / 3;

    cudaFuncSetAttribute(pt_fused_attn,
                         cudaFuncAttributeMaxDynamicSharedMemorySize, SMEM_BYTES);

    pt_detect_idx<<<1, 256>>>((const unsigned*)nb_inds);
    pt_convert_idx<<<(N * HH + 255) / 256, 256>>>(nb_inds, N * HH);
    pt_prepack_w<<<(768 * 256 + 255) / 256, 256>>>(Wq, bq, Wk, bk, Wv, bv);
    pt_cvt_a<<<(MPAD * 256) / 256, 256>>>(s_feats, N);

    dim3 ggrid((N + 127) / 128, 6);
    pt_qkv_gemm_mma<<<ggrid, 256>>>(N);

    int fgrid = 148;
    if (fgrid * 2 > N) fgrid = (N + 1) / 2;
    pt_fused_attn<<<fgrid, 512, SMEM_BYTES>>>(q_pts, s_pts,
                                              Wd1, bd1, Wd2, bd2,
                                              Wa1, ba1, Wa2, ba2,
                                              out, N);
}

// round 6
// speedup vs baseline: 2.3973x; 1.3050x over previous
#include <cuda_runtime.h>
#include <cuda_bf16.h>

// ---------------------------------------------------------------------------
// point_transformer, Round 6
//   - fused-attention stage 2 (geom = hid @ Wd2) moved to mma.sync bf16
//     hi/lo split; h-pairs re-keyed to (h, h+8) to match D-fragment rows
//   - GEMM unchanged from R5 (mma.sync bf16 split)
// ---------------------------------------------------------------------------
#define NMAX 50000
#define MPAD 50048     // 391 * 128
#define HH   16

typedef unsigned long long ull;

__device__ float g_qkv[NMAX * 768];     // [n][0:256)=q [256:512)=k [512:768)=v
__device__ int   g_inds[NMAX * HH];
__device__ int   g_is32;
__device__ float g_bcat[768];
__device__ __nv_bfloat16 g_ahi[MPAD * 256];
__device__ __nv_bfloat16 g_alo[MPAD * 256];
__device__ __nv_bfloat16 g_whiT[768 * 256];    // Wcat^T: [n][k]
__device__ __nv_bfloat16 g_wloT[768 * 256];
__device__ __nv_bfloat16 g_wd2hiT[256 * 64];   // Wd2^T: [c][d]
__device__ __nv_bfloat16 g_wd2loT[256 * 64];

static __device__ __forceinline__ float lrelu(float x) {
    return fmaxf(x, 0.1f * x);
}
static __device__ __forceinline__ ull ffma2(ull a, ull b, ull c) {
    ull d;
    asm("fma.rn.f32x2 %0, %1, %2, %3;" : "=l"(d) : "l"(a), "l"(b), "l"(c));
    return d;
}
static __device__ __forceinline__ ull addf2(ull a, ull b) {
    ull d;
    asm("add.rn.f32x2 %0, %1, %2;" : "=l"(d) : "l"(a), "l"(b));
    return d;
}
static __device__ __forceinline__ ull pack2(float x, float y) {
    ull r;
    asm("mov.b64 %0, {%1, %2};" : "=l"(r) : "f"(x), "f"(y));
    return r;
}
static __device__ __forceinline__ float2 unpack2(ull v) {
    float2 f;
    asm("mov.b64 {%0, %1}, %2;" : "=f"(f.x), "=f"(f.y) : "l"(v));
    return f;
}
static __device__ __forceinline__ void mma_bf16(float* d, const unsigned* a,
                                                const unsigned* b) {
    asm volatile(
        "mma.sync.aligned.m16n8k16.row.col.f32.bf16.bf16.f32 "
        "{%0,%1,%2,%3}, {%4,%5,%6,%7}, {%8,%9}, {%0,%1,%2,%3};"
        : "+f"(d[0]), "+f"(d[1]), "+f"(d[2]), "+f"(d[3])
        : "r"(a[0]), "r"(a[1]), "r"(a[2]), "r"(a[3]), "r"(b[0]), "r"(b[1]));
}
static __device__ __forceinline__ ull pack4bf_hi(float a, float b, float c, float d) {
    unsigned short u0 = __bfloat16_as_ushort(__float2bfloat16(a));
    unsigned short u1 = __bfloat16_as_ushort(__float2bfloat16(b));
    unsigned short u2 = __bfloat16_as_ushort(__float2bfloat16(c));
    unsigned short u3 = __bfloat16_as_ushort(__float2bfloat16(d));
    return (ull)u0 | ((ull)u1 << 16) | ((ull)u2 << 32) | ((ull)u3 << 48);
}

// --------------------------- index dtype handling ---------------------------
__global__ void pt_detect_idx(const unsigned* __restrict__ w) {
    __shared__ int flag;
    if (threadIdx.x == 0) flag = 0;
    __syncthreads();
    unsigned v = w[2 * threadIdx.x + 1];   // int64: odd words are zero
    if (v != 0u) flag = 1;
    __syncthreads();
    if (threadIdx.x == 0) g_is32 = flag;
}

__global__ void pt_convert_idx(const void* __restrict__ p, int total) {
    int i = blockIdx.x * blockDim.x + threadIdx.x;
    if (i >= total) return;
    if (g_is32) g_inds[i] = ((const int*)p)[i];
    else        g_inds[i] = (int)(((const long long*)p)[i]);
}

// --------------------------- prepacks ---------------------------------------
__global__ void pt_prepack_w(const float* __restrict__ Wq, const float* __restrict__ bq,
                             const float* __restrict__ Wk, const float* __restrict__ bk,
                             const float* __restrict__ Wv, const float* __restrict__ bv,
                             const float* __restrict__ Wd2) {
    int i = blockIdx.x * blockDim.x + threadIdx.x;
    if (i < 768 * 256) {
        int n = i >> 8, k = i & 255;
        float w;
        if      (n < 256) w = Wq[k * 256 + n];
        else if (n < 512) w = Wk[k * 256 + (n - 256)];
        else              w = Wv[k * 256 + (n - 512)];
        __nv_bfloat16 hi = __float2bfloat16(w);
        float lo = w - __bfloat162float(hi);
        g_whiT[i] = hi;
        g_wloT[i] = __float2bfloat16(lo);
    }
    if (i < 256 * 64) {
        int c = i >> 6, d = i & 63;
        float w = Wd2[d * 256 + c];
        __nv_bfloat16 hi = __float2bfloat16(w);
        float lo = w - __bfloat162float(hi);
        g_wd2hiT[i] = hi;
        g_wd2loT[i] = __float2bfloat16(lo);
    }
    if (i < 768) {
        g_bcat[i] = (i < 256) ? bq[i] : (i < 512 ? bk[i - 256] : bv[i - 512]);
    }
}

__global__ void pt_cvt_a(const float* __restrict__ A, int M) {
    int i = blockIdx.x * blockDim.x + threadIdx.x;
    if (i >= MPAD * 256) return;
    int row = i >> 8;
    float a = (row < M) ? A[i] : 0.f;
    __nv_bfloat16 hi = __float2bfloat16(a);
    float lo = a - __bfloat162float(hi);
    g_ahi[i] = hi;
    g_alo[i] = __float2bfloat16(lo);
}

// --------------------------- mma.sync QKV GEMM ------------------------------
#define SK 40

__global__ void __launch_bounds__(256, 2)
pt_qkv_gemm_mma(int M) {
    __shared__ __align__(16) __nv_bfloat16 smAhi[128 * SK];
    __shared__ __align__(16) __nv_bfloat16 smAlo[128 * SK];
    __shared__ __align__(16) __nv_bfloat16 smBhi[128 * SK];
    __shared__ __align__(16) __nv_bfloat16 smBlo[128 * SK];

    const int t    = threadIdx.x;
    const int warp = t >> 5;
    const int lane = t & 31;
    const int gid  = lane >> 2;
    const int tq   = lane & 3;
    const int m0 = blockIdx.x * 128;
    const int n0 = blockIdx.y * 128;
    const int mw = (warp & 1) * 64;
    const int nw = (warp >> 1) * 32;

    float acc[4][4][4];
    #pragma unroll
    for (int mt = 0; mt < 4; mt++)
        #pragma unroll
        for (int nt = 0; nt < 4; nt++)
            #pragma unroll
            for (int r = 0; r < 4; r++) acc[mt][nt][r] = 0.f;

    for (int kc = 0; kc < 8; kc++) {
        const int k0 = kc * 32;
        __syncthreads();
        #pragma unroll
        for (int u = 0; u < 2; u++) {
            int q   = t + u * 256;
            int row = q >> 2;
            int kq  = q & 3;
            int dst = row * SK + kq * 8;
            int asrc = (m0 + row) * 256 + k0 + kq * 8;
            int bsrc = (n0 + row) * 256 + k0 + kq * 8;
            *(uint4*)&smAhi[dst] = *(const uint4*)&g_ahi[asrc];
            *(uint4*)&smAlo[dst] = *(const uint4*)&g_alo[asrc];
            *(uint4*)&smBhi[dst] = *(const uint4*)&g_whiT[bsrc];
            *(uint4*)&smBlo[dst] = *(const uint4*)&g_wloT[bsrc];
        }
        __syncthreads();

        #pragma unroll
        for (int ks = 0; ks < 2; ks++) {
            const int kk = ks * 16 + tq * 2;
            unsigned bh[4][2], bl[4][2];
            #pragma unroll
            for (int nt = 0; nt < 4; nt++) {
                const int nr = nw + nt * 8 + gid;
                bh[nt][0] = *(const unsigned*)&smBhi[nr * SK + kk];
                bh[nt][1] = *(const unsigned*)&smBhi[nr * SK + kk + 8];
                bl[nt][0] = *(const unsigned*)&smBlo[nr * SK + kk];
                bl[nt][1] = *(const unsigned*)&smBlo[nr * SK + kk + 8];
            }
            #pragma unroll
            for (int mt = 0; mt < 4; mt++) {
                const int mr = mw + mt * 16 + gid;
                unsigned ah[4], al[4];
                ah[0] = *(const unsigned*)&smAhi[ mr      * SK + kk];
                ah[1] = *(const unsigned*)&smAhi[(mr + 8) * SK + kk];
                ah[2] = *(const unsigned*)&smAhi[ mr      * SK + kk + 8];
                ah[3] = *(const unsigned*)&smAhi[(mr + 8) * SK + kk + 8];
                al[0] = *(const unsigned*)&smAlo[ mr      * SK + kk];
                al[1] = *(const unsigned*)&smAlo[(mr + 8) * SK + kk];
                al[2] = *(const unsigned*)&smAlo[ mr      * SK + kk + 8];
                al[3] = *(const unsigned*)&smAlo[(mr + 8) * SK + kk + 8];
                #pragma unroll
                for (int nt = 0; nt < 4; nt++) {
                    mma_bf16(acc[mt][nt], ah, bh[nt]);
                    mma_bf16(acc[mt][nt], ah, bl[nt]);
                    mma_bf16(acc[mt][nt], al, bh[nt]);
                }
            }
        }
    }

    #pragma unroll
    for (int mt = 0; mt < 4; mt++) {
        const int r0 = m0 + mw + mt * 16 + gid;
        const int r1 = r0 + 8;
        #pragma unroll
        for (int nt = 0; nt < 4; nt++) {
            const int col = n0 + nw + nt * 8 + tq * 2;
            const float b0 = g_bcat[col], b1 = g_bcat[col + 1];
            if (r0 < M) {
                float2 o = make_float2(acc[mt][nt][0] + b0, acc[mt][nt][1] + b1);
                *(float2*)&g_qkv[r0 * 768 + col] = o;
            }
            if (r1 < M) {
                float2 o = make_float2(acc[mt][nt][2] + b0, acc[mt][nt][3] + b1);
                *(float2*)&g_qkv[r1 * 768 + col] = o;
            }
        }
    }
}

// --------------------------- fused attention --------------------------------
// 512 threads = two independent 256-thread halves (named barriers 1/2).
// h-pair convention throughout: pair hp = (h=hp, h=hp+8).
#define OFF_WD2H  0        // bf16 [256][72] -> 9216 floats
#define OFF_WD2L  9216     // bf16 [256][72]
#define OFF_WA2   18432    // [32][32]
#define OFF_WD1   19456    // [3][64]
#define OFF_BD1   19648
#define OFF_BD2   19712
#define OFF_BA1   19968
#define OFF_BA2   20000
#define WEIGHT_FLOATS 20032

#define PP_HIDH   0        // bf16 [16][72] = 576 floats
#define PP_HIDL   576      // bf16 [16][72]
#define PP_GEOM   1152     // ull [8][260] = 4160 floats
#define PP_A2     5312     // ull [8][258] = 4128 floats
#define PP_PART   9440     // ull [8][8][32] = 4096 floats
#define PP_L1     13536    // [16][34]
#define PP_L2     14080    // [16][34]
#define PP_ATTN   14624    // ull [8][34] = 544 floats
#define PP_INDS   15168    // 16 ints
#define PP_QPT    15184    // 3 floats + pad
#define PP_FLOATS 15188

#define SMEM_FLOATS (WEIGHT_FLOATS + 2 * PP_FLOATS)
#define SMEM_BYTES  (SMEM_FLOATS * 4)

#define HBAR(id) asm volatile("bar.sync %0, 256;" :: "r"(id) : "memory")

extern __shared__ float sm_dyn[];

__global__ void __launch_bounds__(512, 1)
pt_fused_attn(const float* __restrict__ q_pts,
              const float* __restrict__ s_pts,
              const float* __restrict__ Wd1, const float* __restrict__ bd1,
              const float* __restrict__ bd2,
              const float* __restrict__ Wa1, const float* __restrict__ ba1,
              const float* __restrict__ Wa2, const float* __restrict__ ba2,
              float* __restrict__ out, int N) {
    float* sm = sm_dyn;
    __nv_bfloat16* Wd2THs = (__nv_bfloat16*)(sm + OFF_WD2H);  // [256 c][72 d]
    __nv_bfloat16* Wd2TLs = (__nv_bfloat16*)(sm + OFF_WD2L);
    float* Wa2s = sm + OFF_WA2;
    float* Wd1s = sm + OFF_WD1;
    float* bd1s = sm + OFF_BD1;
    float* bd2s = sm + OFF_BD2;
    float* ba1s = sm + OFF_BA1;
    float* ba2s = sm + OFF_BA2;

    const int t   = threadIdx.x;
    const int pid = t >> 8;
    const int tt  = t & 255;
    const int ww  = (t >> 5) & 7;   // warp in half: owns channels [32ww, 32ww+32)
    const int l   = t & 31;
    const int gid = l >> 2;         // 0..7
    const int tq  = l & 3;          // 0..3
    const int bid = pid + 1;

    float* pp     = sm + WEIGHT_FLOATS + pid * PP_FLOATS;
    __nv_bfloat16* hidHi = (__nv_bfloat16*)(pp + PP_HIDH);   // [16 h][72 d]
    __nv_bfloat16* hidLo = (__nv_bfloat16*)(pp + PP_HIDL);
    ull*   geom2  = (ull*)(pp + PP_GEOM);   // [8 hp][260 c], pair (hp, hp+8)
    ull*   a2u    = (ull*)(pp + PP_A2);     // [8 hp][258 c]
    ull*   partu  = (ull*)(pp + PP_PART);
    float* l1s    = pp + PP_L1;
    float* l2s    = pp + PP_L2;
    ull*   attn2  = (ull*)(pp + PP_ATTN);
    int*   inds_s = (int*)(pp + PP_INDS);
    float* qptf   = pp + PP_QPT;

    // persistent Wa1 register cache: wreg[j] = Wa1[32*ww + j][l]
    float wreg[32];
    #pragma unroll
    for (int j = 0; j < 32; j++)
        wreg[j] = Wa1[(ww * 32 + j) * 32 + l];

    // stage 0: weights -> shared
    for (int i = t; i < 256 * 16; i += 512) {   // 4096 ull covers 256*64 bf16
        int n = i >> 4, k4 = (i & 15) * 4;
        *(ull*)&Wd2THs[n * 72 + k4] = ((const ull*)g_wd2hiT)[i];
        *(ull*)&Wd2TLs[n * 72 + k4] = ((const ull*)g_wd2loT)[i];
    }
    for (int i = t; i < 1024; i += 512) Wa2s[i] = Wa2[i];
    if (t < 192) Wd1s[t] = Wd1[t];
    if (t < 64)  bd1s[t] = bd1[t];
    if (t < 256) bd2s[t] = bd2[t];
    if (t < 32) { ba1s[t] = ba1[t]; ba2s[t] = ba2[t]; }
    __syncthreads();

    for (int n2 = blockIdx.x; n2 * 2 < N; n2 += gridDim.x) {
        const int nreq = n2 * 2 + pid;
        const int n = (nreq < N) ? nreq : (N - 1);
        const bool do_store = (nreq < N);

        if (tt < 16) inds_s[tt] = g_inds[n * 16 + tt];
        if (tt < 3)  qptf[tt]   = q_pts[n * 3 + tt];
        HBAR(bid);

        // prefetch nk + qf (L2 latency hidden behind stage 1 + mma)
        float nk[16];
        const float qf = g_qkv[inds_s[0] * 768 + tt];
        #pragma unroll
        for (int h = 0; h < 16; h++)
            nk[h] = g_qkv[inds_s[h] * 768 + 256 + tt];

        // stage 1: hidden = lrelu(rel @ Wd1 + bd1), stored bf16 hi/lo [h][72]
        {
            const int h  = tt >> 4;
            const int d0 = (tt & 15) << 2;
            const int j  = inds_s[h];
            const float rx = s_pts[j * 3 + 0] - qptf[0];
            const float ry = s_pts[j * 3 + 1] - qptf[1];
            const float rz = s_pts[j * 3 + 2] - qptf[2];
            float vv[4], vh[4], vl[4];
            #pragma unroll
            for (int i = 0; i < 4; i++) {
                const int d = d0 + i;
                float v = rx * Wd1s[d] + ry * Wd1s[64 + d] + rz * Wd1s[128 + d] + bd1s[d];
                vv[i] = lrelu(v);
                vh[i] = __bfloat162float(__float2bfloat16(vv[i]));
                vl[i] = vv[i] - vh[i];
            }
            *(ull*)&hidHi[h * 72 + d0] = pack4bf_hi(vh[0], vh[1], vh[2], vh[3]);
            *(ull*)&hidLo[h * 72 + d0] = pack4bf_hi(vl[0], vl[1], vl[2], vl[3]);
        }
        HBAR(bid);

        // stage 2: geom = hid @ Wd2 via mma.sync (hi/lo split).
        // Warp ww covers channels [32ww, 32ww+32). D rows = (gid, gid+8).
        {
            float acc[4][4];
            #pragma unroll
            for (int nt = 0; nt < 4; nt++)
                #pragma unroll
                for (int r = 0; r < 4; r++) acc[nt][r] = 0.f;

            #pragma unroll
            for (int kc = 0; kc < 4; kc++) {
                const int k0 = kc * 16;
                unsigned ah[4], al[4];
                ah[0] = *(const unsigned*)&hidHi[ gid      * 72 + k0 + tq * 2];
                ah[1] = *(const unsigned*)&hidHi[(gid + 8) * 72 + k0 + tq * 2];
                ah[2] = *(const unsigned*)&hidHi[ gid      * 72 + k0 + 8 + tq * 2];
                ah[3] = *(const unsigned*)&hidHi[(gid + 8) * 72 + k0 + 8 + tq * 2];
                al[0] = *(const unsigned*)&hidLo[ gid      * 72 + k0 + tq * 2];
                al[1] = *(const unsigned*)&hidLo[(gid + 8) * 72 + k0 + tq * 2];
                al[2] = *(const unsigned*)&hidLo[ gid      * 72 + k0 + 8 + tq * 2];
                al[3] = *(const unsigned*)&hidLo[(gid + 8) * 72 + k0 + 8 + tq * 2];
                #pragma unroll
                for (int nt = 0; nt < 4; nt++) {
                    const int nr = ww * 32 + nt * 8 + gid;
                    unsigned bh[2], bl[2];
                    bh[0] = *(const unsigned*)&Wd2THs[nr * 72 + k0 + tq * 2];
                    bh[1] = *(const unsigned*)&Wd2THs[nr * 72 + k0 + 8 + tq * 2];
                    bl[0] = *(const unsigned*)&Wd2TLs[nr * 72 + k0 + tq * 2];
                    bl[1] = *(const unsigned*)&Wd2TLs[nr * 72 + k0 + 8 + tq * 2];
                    mma_bf16(acc[nt], ah, bh);
                    mma_bf16(acc[nt], ah, bl);
                    mma_bf16(acc[nt], al, bh);
                }
            }
            // write geom pairs (h=gid, h=gid+8) + bias
            #pragma unroll
            for (int nt = 0; nt < 4; nt++) {
                const int c0 = ww * 32 + nt * 8 + tq * 2;
                const float b0 = bd2s[c0], b1 = bd2s[c0 + 1];
                geom2[gid * 260 + c0    ] = pack2(acc[nt][0] + b0, acc[nt][2] + b0);
                geom2[gid * 260 + c0 + 1] = pack2(acc[nt][1] + b1, acc[nt][3] + b1);
            }
        }

        // prefetch nv (acc registers are dead now; overlaps barrier + stage 3)
        float nv[16];
        #pragma unroll
        for (int h = 0; h < 16; h++)
            nv[h] = g_qkv[inds_s[h] * 768 + 512 + tt];
        HBAR(bid);

        // stage 3: read geom pairs, a = lrelu(qf - nk - geom) -> smem
        ull g[8];
        #pragma unroll
        for (int hp = 0; hp < 8; hp++) {
            g[hp] = geom2[hp * 260 + tt];
            const float2 gp = unpack2(g[hp]);
            const float ax = lrelu(qf - nk[hp]     - gp.x);
            const float ay = lrelu(qf - nk[hp + 8] - gp.y);
            a2u[hp * 258 + tt] = pack2(ax, ay);
        }
        HBAR(bid);

        // stage 4: partial[ww][hp][m=l] from register Wa1 + broadcast LDS.128
        {
            ull acc[8];
            #pragma unroll
            for (int hp = 0; hp < 8; hp++) acc[hp] = 0ull;
            const int cbase = ww * 32;
            #pragma unroll
            for (int jv = 0; jv < 16; jv++) {
                const ull w0 = pack2(wreg[2*jv],     wreg[2*jv]);
                const ull w1 = pack2(wreg[2*jv + 1], wreg[2*jv + 1]);
                #pragma unroll
                for (int hp = 0; hp < 8; hp++) {
                    ulonglong2 av = *(const ulonglong2*)&a2u[hp * 258 + cbase + 2*jv];
                    acc[hp] = ffma2(av.x, w0, acc[hp]);
                    acc[hp] = ffma2(av.y, w1, acc[hp]);
                }
            }
            #pragma unroll
            for (int hp = 0; hp < 8; hp++)
                partu[(ww * 8 + hp) * 32 + l] = acc[hp];
        }
        HBAR(bid);

        // stage 4b: reduce warp partials, bias, lrelu -> l1s rows (hp, hp+8)
        {
            const int hp = tt >> 5;
            const int m  = tt & 31;
            const float b = ba1s[m];
            ull s = pack2(b, b);
            #pragma unroll
            for (int w8 = 0; w8 < 8; w8++)
                s = addf2(s, partu[(w8 * 8 + hp) * 32 + m]);
            float2 v = unpack2(s);
            l1s[ hp      * 34 + m] = lrelu(v.x);
            l1s[(hp + 8) * 34 + m] = lrelu(v.y);
        }
        HBAR(bid);

        // stage 5: logits2 = l1 @ Wa2 + ba2
        {
            const int h  = tt >> 4;
            const int m0 = (tt & 15) * 2;
            ull acc01 = pack2(ba2s[m0], ba2s[m0 + 1]);
            const float* lrow = l1s + h * 34;
            #pragma unroll
            for (int jj = 0; jj < 32; jj++) {
                const float lv = lrow[jj];
                ull w = *(const ull*)(Wa2s + jj * 32 + m0);
                acc01 = ffma2(pack2(lv, lv), w, acc01);
            }
            float2 r = unpack2(acc01);
            l2s[h * 34 + m0    ] = r.x;
            l2s[h * 34 + m0 + 1] = r.y;
        }
        HBAR(bid);

        // stage 6: softmax over h; attn pairs (hp, hp+8)
        if (tt < 32) {
            float vals[16];
            float mx = -3.4e38f;
            #pragma unroll
            for (int h = 0; h < 16; h++) {
                vals[h] = l2s[h * 34 + tt];
                mx = fmaxf(mx, vals[h]);
            }
            float s = 0.f;
            #pragma unroll
            for (int h = 0; h < 16; h++) {
                vals[h] = __expf(vals[h] - mx);
                s += vals[h];
            }
            const float inv = 1.f / s;
            #pragma unroll
            for (int hp = 0; hp < 8; hp++)
                attn2[hp * 34 + tt] = pack2(vals[hp] * inv, vals[hp + 8] * inv);
        }
        HBAR(bid);

        // stage 7: out[c] = sum_h (nv[h]-geom[h]) * attn[h][c>>3]
        {
            const int mg = tt >> 3;
            ull acc2p = 0ull;
            #pragma unroll
            for (int hp = 0; hp < 8; hp++) {
                const float2 gp = unpack2(g[hp]);
                ull vm = pack2(nv[hp] - gp.x, nv[hp + 8] - gp.y);
                acc2p = ffma2(vm, attn2[hp * 34 + mg], acc2p);
            }
            float2 r = unpack2(acc2p);
            if (do_store) out[n * 256 + tt] = r.x + r.y;
        }
    }
}

// --------------------------- launch ------------------------------------------
extern "C" void kernel_launch(void* const* d_in, const int* in_sizes, int n_in,
                              void* d_out, int out_size) {
    const float* q_pts   = (const float*)d_in[0];
    const float* s_pts   = (const float*)d_in[1];
    const float* s_feats = (const float*)d_in[2];
    const void*  nb_inds = d_in[3];
    const float* Wq = (const float*)d_in[4];
    const float* bq = (const float*)d_in[5];
    const float* Wk = (const float*)d_in[6];
    const float* bk = (const float*)d_in[7];
    const float* Wv = (const float*)d_in[8];
    const float* bv = (const float*)d_in[9];
    const float* Wd1 = (const float*)d_in[10];
    const float* bd1 = (const float*)d_in[11];
    const float* Wd2 = (const float*)d_in[12];
    const float* bd2 = (const float*)d_in[13];
    const float* Wa1 = (const float*)d_in[14];
    const float* ba1 = (const float*)d_in[15];
    const float* Wa2 = (const float*)d_in[16];
    const float* ba2 = (const float*)d_in[17];
    float* out = (float*)d_out;

    const int N = in_sizes[0] / 3;

    cudaFuncSetAttribute(pt_fused_attn,
                         cudaFuncAttributeMaxDynamicSharedMemorySize, SMEM_BYTES);

    pt_detect_idx<<<1, 256>>>((const unsigned*)nb_inds);
    pt_convert_idx<<<(N * HH + 255) / 256, 256>>>(nb_inds, N * HH);
    pt_prepack_w<<<(768 * 256 + 255) / 256, 256>>>(Wq, bq, Wk, bk, Wv, bv, Wd2);
    pt_cvt_a<<<(MPAD * 256) / 256, 256>>>(s_feats, N);

    dim3 ggrid((N + 127) / 128, 6);
    pt_qkv_gemm_mma<<<ggrid, 256>>>(N);

    int fgrid = 148;
    if (fgrid * 2 > N) fgrid = (N + 1) / 2;
    pt_fused_attn<<<fgrid, 512, SMEM_BYTES>>>(q_pts, s_pts,
                                              Wd1, bd1, bd2,
                                              Wa1, ba1, Wa2, ba2,
                                              out, N);
}

// round 7
// speedup vs baseline: 3.1549x; 1.3160x over previous
#include <cuda_runtime.h>
#include <cuda_bf16.h>

// ---------------------------------------------------------------------------
// point_transformer, Round 7
//   - fused stage 4 (a @ Wa1) tensorized: bf16 hi/lo mma.sync, Wa1 fragments
//     persistent in registers; a written to smem as bf16 hi/lo tiles
//   - QKV GEMM double-buffered with cp.async (load/MMA overlap)
// ---------------------------------------------------------------------------
#define NMAX 50000
#define MPAD 50048     // 391 * 128
#define HH   16

typedef unsigned long long ull;

__device__ float g_qkv[NMAX * 768];     // [n][0:256)=q [256:512)=k [512:768)=v
__device__ int   g_inds[NMAX * HH];
__device__ int   g_is32;
__device__ float g_bcat[768];
__device__ __nv_bfloat16 g_ahi[MPAD * 256];
__device__ __nv_bfloat16 g_alo[MPAD * 256];
__device__ __nv_bfloat16 g_whiT[768 * 256];    // Wcat^T: [n][k]
__device__ __nv_bfloat16 g_wloT[768 * 256];
__device__ __nv_bfloat16 g_wd2hiT[256 * 64];   // Wd2^T: [c][d]
__device__ __nv_bfloat16 g_wd2loT[256 * 64];
__device__ __nv_bfloat16 g_wa1hiT[32 * 256];   // Wa1^T: [m][c]
__device__ __nv_bfloat16 g_wa1loT[32 * 256];

static __device__ __forceinline__ float lrelu(float x) {
    return fmaxf(x, 0.1f * x);
}
static __device__ __forceinline__ ull ffma2(ull a, ull b, ull c) {
    ull d;
    asm("fma.rn.f32x2 %0, %1, %2, %3;" : "=l"(d) : "l"(a), "l"(b), "l"(c));
    return d;
}
static __device__ __forceinline__ ull addf2(ull a, ull b) {
    ull d;
    asm("add.rn.f32x2 %0, %1, %2;" : "=l"(d) : "l"(a), "l"(b));
    return d;
}
static __device__ __forceinline__ ull pack2(float x, float y) {
    ull r;
    asm("mov.b64 %0, {%1, %2};" : "=l"(r) : "f"(x), "f"(y));
    return r;
}
static __device__ __forceinline__ float2 unpack2(ull v) {
    float2 f;
    asm("mov.b64 {%0, %1}, %2;" : "=f"(f.x), "=f"(f.y) : "l"(v));
    return f;
}
static __device__ __forceinline__ void mma_bf16(float* d, const unsigned* a,
                                                const unsigned* b) {
    asm volatile(
        "mma.sync.aligned.m16n8k16.row.col.f32.bf16.bf16.f32 "
        "{%0,%1,%2,%3}, {%4,%5,%6,%7}, {%8,%9}, {%0,%1,%2,%3};"
        : "+f"(d[0]), "+f"(d[1]), "+f"(d[2]), "+f"(d[3])
        : "r"(a[0]), "r"(a[1]), "r"(a[2]), "r"(a[3]), "r"(b[0]), "r"(b[1]));
}
static __device__ __forceinline__ ull pack4bf_hi(float a, float b, float c, float d) {
    unsigned short u0 = __bfloat16_as_ushort(__float2bfloat16(a));
    unsigned short u1 = __bfloat16_as_ushort(__float2bfloat16(b));
    unsigned short u2 = __bfloat16_as_ushort(__float2bfloat16(c));
    unsigned short u3 = __bfloat16_as_ushort(__float2bfloat16(d));
    return (ull)u0 | ((ull)u1 << 16) | ((ull)u2 << 32) | ((ull)u3 << 48);
}
static __device__ __forceinline__ unsigned smem_u32(const void* p) {
    unsigned a;
    asm("{ .reg .u64 t; cvta.to.shared.u64 t, %1; cvt.u32.u64 %0, t; }"
        : "=r"(a) : "l"(p));
    return a;
}
static __device__ __forceinline__ void cp16(unsigned smaddr, const void* g) {
    asm volatile("cp.async.cg.shared.global [%0], [%1], 16;"
                 :: "r"(smaddr), "l"(g) : "memory");
}
#define CP_COMMIT() asm volatile("cp.async.commit_group;" ::: "memory")
#define CP_WAIT(n)  asm volatile("cp.async.wait_group %0;" :: "n"(n) : "memory")

// --------------------------- index dtype handling ---------------------------
__global__ void pt_detect_idx(const unsigned* __restrict__ w) {
    __shared__ int flag;
    if (threadIdx.x == 0) flag = 0;
    __syncthreads();
    unsigned v = w[2 * threadIdx.x + 1];   // int64: odd words are zero
    if (v != 0u) flag = 1;
    __syncthreads();
    if (threadIdx.x == 0) g_is32 = flag;
}

__global__ void pt_convert_idx(const void* __restrict__ p, int total) {
    int i = blockIdx.x * blockDim.x + threadIdx.x;
    if (i >= total) return;
    if (g_is32) g_inds[i] = ((const int*)p)[i];
    else        g_inds[i] = (int)(((const long long*)p)[i]);
}

// --------------------------- prepacks ---------------------------------------
__global__ void pt_prepack_w(const float* __restrict__ Wq, const float* __restrict__ bq,
                             const float* __restrict__ Wk, const float* __restrict__ bk,
                             const float* __restrict__ Wv, const float* __restrict__ bv,
                             const float* __restrict__ Wd2, const float* __restrict__ Wa1) {
    int i = blockIdx.x * blockDim.x + threadIdx.x;
    if (i < 768 * 256) {
        int n = i >> 8, k = i & 255;
        float w;
        if      (n < 256) w = Wq[k * 256 + n];
        else if (n < 512) w = Wk[k * 256 + (n - 256)];
        else              w = Wv[k * 256 + (n - 512)];
        __nv_bfloat16 hi = __float2bfloat16(w);
        float lo = w - __bfloat162float(hi);
        g_whiT[i] = hi;
        g_wloT[i] = __float2bfloat16(lo);
    }
    if (i < 256 * 64) {
        int c = i >> 6, d = i & 63;
        float w = Wd2[d * 256 + c];
        __nv_bfloat16 hi = __float2bfloat16(w);
        float lo = w - __bfloat162float(hi);
        g_wd2hiT[i] = hi;
        g_wd2loT[i] = __float2bfloat16(lo);
    }
    if (i < 32 * 256) {
        int m = i >> 8, k = i & 255;
        float w = Wa1[k * 32 + m];
        __nv_bfloat16 hi = __float2bfloat16(w);
        float lo = w - __bfloat162float(hi);
        g_wa1hiT[i] = hi;
        g_wa1loT[i] = __float2bfloat16(lo);
    }
    if (i < 768) {
        g_bcat[i] = (i < 256) ? bq[i] : (i < 512 ? bk[i - 256] : bv[i - 512]);
    }
}

__global__ void pt_cvt_a(const float* __restrict__ A, int M) {
    int i = blockIdx.x * blockDim.x + threadIdx.x;
    if (i >= MPAD * 256) return;
    int row = i >> 8;
    float a = (row < M) ? A[i] : 0.f;
    __nv_bfloat16 hi = __float2bfloat16(a);
    float lo = a - __bfloat162float(hi);
    g_ahi[i] = hi;
    g_alo[i] = __float2bfloat16(lo);
}

// --------------------------- mma.sync QKV GEMM (cp.async x2 buf) ------------
#define SK 40
#define TILE_BYTES  (128 * SK * 2)      // 10240
#define STAGE_BYTES (4 * TILE_BYTES)    // 40960: Ahi|Alo|Bhi|Blo
#define GEMM_SMEM   (2 * STAGE_BYTES)   // 81920

extern __shared__ char sm_raw[];

__global__ void __launch_bounds__(256, 2)
pt_qkv_gemm_mma(int M) {
    char* gsm = sm_raw;
    const unsigned sbase = smem_u32(gsm);

    const int t    = threadIdx.x;
    const int warp = t >> 5;
    const int lane = t & 31;
    const int gid  = lane >> 2;
    const int tq   = lane & 3;
    const int m0 = blockIdx.x * 128;
    const int n0 = blockIdx.y * 128;
    const int mw = (warp & 1) * 64;
    const int nw = (warp >> 1) * 32;

    // per-thread fixed copy slots
    const int row0 = t >> 2;            // 0..63   (u=0)
    const int kq0  = t & 3;
    const int row1 = (t + 256) >> 2;    // 64..127 (u=1)
    const int kq1  = kq0;

    float acc[4][4][4];
    #pragma unroll
    for (int mt = 0; mt < 4; mt++)
        #pragma unroll
        for (int nt = 0; nt < 4; nt++)
            #pragma unroll
            for (int r = 0; r < 4; r++) acc[mt][nt][r] = 0.f;

    // issue k-chunk kc into buffer buf
    auto issue = [&](int kc, int buf) {
        const int k0 = kc * 32;
        const unsigned sb = sbase + buf * STAGE_BYTES;
        {
            unsigned dst = sb + (row0 * SK + kq0 * 8) * 2;
            int asrc = (m0 + row0) * 256 + k0 + kq0 * 8;
            int bsrc = (n0 + row0) * 256 + k0 + kq0 * 8;
            cp16(dst + 0 * TILE_BYTES, &g_ahi[asrc]);
            cp16(dst + 1 * TILE_BYTES, &g_alo[asrc]);
            cp16(dst + 2 * TILE_BYTES, &g_whiT[bsrc]);
            cp16(dst + 3 * TILE_BYTES, &g_wloT[bsrc]);
        }
        {
            unsigned dst = sb + (row1 * SK + kq1 * 8) * 2;
            int asrc = (m0 + row1) * 256 + k0 + kq1 * 8;
            int bsrc = (n0 + row1) * 256 + k0 + kq1 * 8;
            cp16(dst + 0 * TILE_BYTES, &g_ahi[asrc]);
            cp16(dst + 1 * TILE_BYTES, &g_alo[asrc]);
            cp16(dst + 2 * TILE_BYTES, &g_whiT[bsrc]);
            cp16(dst + 3 * TILE_BYTES, &g_wloT[bsrc]);
        }
        CP_COMMIT();
    };

    issue(0, 0);

    for (int kc = 0; kc < 8; kc++) {
        if (kc < 7) issue(kc + 1, (kc + 1) & 1);
        if (kc < 7) { CP_WAIT(1); } else { CP_WAIT(0); }
        __syncthreads();

        char* base = gsm + (kc & 1) * STAGE_BYTES;
        const __nv_bfloat16* smAhi = (const __nv_bfloat16*)(base);
        const __nv_bfloat16* smAlo = (const __nv_bfloat16*)(base + 1 * TILE_BYTES);
        const __nv_bfloat16* smBhi = (const __nv_bfloat16*)(base + 2 * TILE_BYTES);
        const __nv_bfloat16* smBlo = (const __nv_bfloat16*)(base + 3 * TILE_BYTES);

        #pragma unroll
        for (int ks = 0; ks < 2; ks++) {
            const int kk = ks * 16 + tq * 2;
            unsigned bh[4][2], bl[4][2];
            #pragma unroll
            for (int nt = 0; nt < 4; nt++) {
                const int nr = nw + nt * 8 + gid;
                bh[nt][0] = *(const unsigned*)&smBhi[nr * SK + kk];
                bh[nt][1] = *(const unsigned*)&smBhi[nr * SK + kk + 8];
                bl[nt][0] = *(const unsigned*)&smBlo[nr * SK + kk];
                bl[nt][1] = *(const unsigned*)&smBlo[nr * SK + kk + 8];
            }
            #pragma unroll
            for (int mt = 0; mt < 4; mt++) {
                const int mr = mw + mt * 16 + gid;
                unsigned ah[4], al[4];
                ah[0] = *(const unsigned*)&smAhi[ mr      * SK + kk];
                ah[1] = *(const unsigned*)&smAhi[(mr + 8) * SK + kk];
                ah[2] = *(const unsigned*)&smAhi[ mr      * SK + kk + 8];
                ah[3] = *(const unsigned*)&smAhi[(mr + 8) * SK + kk + 8];
                al[0] = *(const unsigned*)&smAlo[ mr      * SK + kk];
                al[1] = *(const unsigned*)&smAlo[(mr + 8) * SK + kk];
                al[2] = *(const unsigned*)&smAlo[ mr      * SK + kk + 8];
                al[3] = *(const unsigned*)&smAlo[(mr + 8) * SK + kk + 8];
                #pragma unroll
                for (int nt = 0; nt < 4; nt++) {
                    mma_bf16(acc[mt][nt], ah, bh[nt]);
                    mma_bf16(acc[mt][nt], ah, bl[nt]);
                    mma_bf16(acc[mt][nt], al, bh[nt]);
                }
            }
        }
        __syncthreads();
    }

    #pragma unroll
    for (int mt = 0; mt < 4; mt++) {
        const int r0 = m0 + mw + mt * 16 + gid;
        const int r1 = r0 + 8;
        #pragma unroll
        for (int nt = 0; nt < 4; nt++) {
            const int col = n0 + nw + nt * 8 + tq * 2;
            const float b0 = g_bcat[col], b1 = g_bcat[col + 1];
            if (r0 < M) {
                float2 o = make_float2(acc[mt][nt][0] + b0, acc[mt][nt][1] + b1);
                *(float2*)&g_qkv[r0 * 768 + col] = o;
            }
            if (r1 < M) {
                float2 o = make_float2(acc[mt][nt][2] + b0, acc[mt][nt][3] + b1);
                *(float2*)&g_qkv[r1 * 768 + col] = o;
            }
        }
    }
}

// --------------------------- fused attention --------------------------------
// 512 threads = two independent 256-thread halves (named barriers 1/2).
// h-pair convention: pair hp = (h=hp, h=hp+8).
#define OFF_WD2H  0        // bf16 [256][72] -> 9216 floats
#define OFF_WD2L  9216
#define OFF_WA2   18432    // [32][32]
#define OFF_WD1   19456
#define OFF_BD1   19648
#define OFF_BD2   19712
#define OFF_BA1   19968
#define OFF_BA2   20000
#define WEIGHT_FLOATS 20032

#define PP_AH     0        // bf16 [16][264] = 2112 floats
#define PP_AL     2112     // bf16 [16][264]
#define PP_GEOM   4224     // ull [8][260] = 4160 floats
#define PP_PART   8384     // ull [8 ww][8 hp][34] = 4352 floats
#define PP_L1     12736    // [16][34]
#define PP_L2     13280    // [16][34]
#define PP_ATTN   13824    // ull [8][34] = 544 floats
#define PP_INDS   14368    // 16 ints
#define PP_QPT    14384    // 3 floats + pad
#define PP_FLOATS 14388

#define SMEM_FLOATS (WEIGHT_FLOATS + 2 * PP_FLOATS)
#define SMEM_BYTES  (SMEM_FLOATS * 4)

#define HBAR(id) asm volatile("bar.sync %0, 256;" :: "r"(id) : "memory")

__global__ void __launch_bounds__(512, 1)
pt_fused_attn(const float* __restrict__ q_pts,
              const float* __restrict__ s_pts,
              const float* __restrict__ Wd1, const float* __restrict__ bd1,
              const float* __restrict__ bd2,
              const float* __restrict__ ba1,
              const float* __restrict__ Wa2, const float* __restrict__ ba2,
              float* __restrict__ out, int N) {
    float* sm = (float*)sm_raw;
    __nv_bfloat16* Wd2THs = (__nv_bfloat16*)(sm + OFF_WD2H);  // [256 c][72 d]
    __nv_bfloat16* Wd2TLs = (__nv_bfloat16*)(sm + OFF_WD2L);
    float* Wa2s = sm + OFF_WA2;
    float* Wd1s = sm + OFF_WD1;
    float* bd1s = sm + OFF_BD1;
    float* bd2s = sm + OFF_BD2;
    float* ba1s = sm + OFF_BA1;
    float* ba2s = sm + OFF_BA2;

    const int t   = threadIdx.x;
    const int pid = t >> 8;
    const int tt  = t & 255;
    const int ww  = (t >> 5) & 7;   // warp in half: owns c-slice [32ww, 32ww+32)
    const int l   = t & 31;
    const int gid = l >> 2;         // 0..7
    const int tq  = l & 3;          // 0..3
    const int bid = pid + 1;

    float* pp     = sm + WEIGHT_FLOATS + pid * PP_FLOATS;
    __nv_bfloat16* aH = (__nv_bfloat16*)(pp + PP_AH);   // [16 h][264 c]
    __nv_bfloat16* aL = (__nv_bfloat16*)(pp + PP_AL);
    ull*   geom2  = (ull*)(pp + PP_GEOM);   // [8 hp][260 c]
    ull*   partu  = (ull*)(pp + PP_PART);   // [(ww*8+hp)*34 + m]
    float* l1s    = pp + PP_L1;
    float* l2s    = pp + PP_L2;
    ull*   attn2  = (ull*)(pp + PP_ATTN);
    int*   inds_s = (int*)(pp + PP_INDS);
    float* qptf   = pp + PP_QPT;

    // persistent Wa1 B-fragments (bf16 hi/lo): warp ww covers k=c slice
    // [32ww, 32ww+32); n-tile nt covers m = nt*8 + gid.
    unsigned wbh[4][2][2], wbl[4][2][2];
    #pragma unroll
    for (int nt = 0; nt < 4; nt++)
        #pragma unroll
        for (int s = 0; s < 2; s++) {
            const int m  = nt * 8 + gid;
            const int k0 = ww * 32 + s * 16 + tq * 2;
            wbh[nt][s][0] = *(const unsigned*)&g_wa1hiT[m * 256 + k0];
            wbh[nt][s][1] = *(const unsigned*)&g_wa1hiT[m * 256 + k0 + 8];
            wbl[nt][s][0] = *(const unsigned*)&g_wa1loT[m * 256 + k0];
            wbl[nt][s][1] = *(const unsigned*)&g_wa1loT[m * 256 + k0 + 8];
        }

    // stage 0: weights -> shared
    for (int i = t; i < 256 * 16; i += 512) {   // 4096 ull covers 256*64 bf16
        int n = i >> 4, k4 = (i & 15) * 4;
        *(ull*)&Wd2THs[n * 72 + k4] = ((const ull*)g_wd2hiT)[i];
        *(ull*)&Wd2TLs[n * 72 + k4] = ((const ull*)g_wd2loT)[i];
    }
    for (int i = t; i < 1024; i += 512) Wa2s[i] = Wa2[i];
    if (t < 192) Wd1s[t] = Wd1[t];
    if (t < 64)  bd1s[t] = bd1[t];
    if (t < 256) bd2s[t] = bd2[t];
    if (t < 32) { ba1s[t] = ba1[t]; ba2s[t] = ba2[t]; }
    __syncthreads();

    for (int n2 = blockIdx.x; n2 * 2 < N; n2 += gridDim.x) {
        const int nreq = n2 * 2 + pid;
        const int n = (nreq < N) ? nreq : (N - 1);
        const bool do_store = (nreq < N);

        if (tt < 16) inds_s[tt] = g_inds[n * 16 + tt];
        if (tt < 3)  qptf[tt]   = q_pts[n * 3 + tt];
        HBAR(bid);

        // prefetch nk + qf
        float nk[16];
        const float qf = g_qkv[inds_s[0] * 768 + tt];
        #pragma unroll
        for (int h = 0; h < 16; h++)
            nk[h] = g_qkv[inds_s[h] * 768 + 256 + tt];

        // stage 1: hidden = lrelu(rel @ Wd1 + bd1), bf16 hi/lo [h][72]
        // (reuses aH/aL buffers? no - hid has its own region: use geom area?
        //  keep separate: hid tiles live in aH region temporarily)
        {
            const int h  = tt >> 4;
            const int d0 = (tt & 15) << 2;
            const int j  = inds_s[h];
            const float rx = s_pts[j * 3 + 0] - qptf[0];
            const float ry = s_pts[j * 3 + 1] - qptf[1];
            const float rz = s_pts[j * 3 + 2] - qptf[2];
            float vv[4], vh[4], vl[4];
            #pragma unroll
            for (int i = 0; i < 4; i++) {
                const int d = d0 + i;
                float v = rx * Wd1s[d] + ry * Wd1s[64 + d] + rz * Wd1s[128 + d] + bd1s[d];
                vv[i] = lrelu(v);
                vh[i] = __bfloat162float(__float2bfloat16(vv[i]));
                vl[i] = vv[i] - vh[i];
            }
            // hid stored in aH/aL rows with stride 72 (fits: 16*72 < 16*264)
            *(ull*)&aH[h * 72 + d0] = pack4bf_hi(vh[0], vh[1], vh[2], vh[3]);
            *(ull*)&aL[h * 72 + d0] = pack4bf_hi(vl[0], vl[1], vl[2], vl[3]);
        }
        HBAR(bid);

        // stage 2: geom = hid @ Wd2 via mma (hi/lo split); D rows (gid, gid+8)
        {
            float acc[4][4];
            #pragma unroll
            for (int nt = 0; nt < 4; nt++)
                #pragma unroll
                for (int r = 0; r < 4; r++) acc[nt][r] = 0.f;

            #pragma unroll
            for (int kc = 0; kc < 4; kc++) {
                const int k0 = kc * 16;
                unsigned ah[4], al[4];
                ah[0] = *(const unsigned*)&aH[ gid      * 72 + k0 + tq * 2];
                ah[1] = *(const unsigned*)&aH[(gid + 8) * 72 + k0 + tq * 2];
                ah[2] = *(const unsigned*)&aH[ gid      * 72 + k0 + 8 + tq * 2];
                ah[3] = *(const unsigned*)&aH[(gid + 8) * 72 + k0 + 8 + tq * 2];
                al[0] = *(const unsigned*)&aL[ gid      * 72 + k0 + tq * 2];
                al[1] = *(const unsigned*)&aL[(gid + 8) * 72 + k0 + tq * 2];
                al[2] = *(const unsigned*)&aL[ gid      * 72 + k0 + 8 + tq * 2];
                al[3] = *(const unsigned*)&aL[(gid + 8) * 72 + k0 + 8 + tq * 2];
                #pragma unroll
                for (int nt = 0; nt < 4; nt++) {
                    const int nr = ww * 32 + nt * 8 + gid;
                    unsigned bh[2], bl[2];
                    bh[0] = *(const unsigned*)&Wd2THs[nr * 72 + k0 + tq * 2];
                    bh[1] = *(const unsigned*)&Wd2THs[nr * 72 + k0 + 8 + tq * 2];
                    bl[0] = *(const unsigned*)&Wd2TLs[nr * 72 + k0 + tq * 2];
                    bl[1] = *(const unsigned*)&Wd2TLs[nr * 72 + k0 + 8 + tq * 2];
                    mma_bf16(acc[nt], ah, bh);
                    mma_bf16(acc[nt], ah, bl);
                    mma_bf16(acc[nt], al, bh);
                }
            }
            #pragma unroll
            for (int nt = 0; nt < 4; nt++) {
                const int c0 = ww * 32 + nt * 8 + tq * 2;
                const float b0 = bd2s[c0], b1 = bd2s[c0 + 1];
                geom2[gid * 260 + c0    ] = pack2(acc[nt][0] + b0, acc[nt][2] + b0);
                geom2[gid * 260 + c0 + 1] = pack2(acc[nt][1] + b1, acc[nt][3] + b1);
            }
        }

        // prefetch nv
        float nv[16];
        #pragma unroll
        for (int h = 0; h < 16; h++)
            nv[h] = g_qkv[inds_s[h] * 768 + 512 + tt];
        HBAR(bid);

        // stage 3: a = lrelu(qf - nk - geom); store bf16 hi/lo [16][264]
        ull g[8];
        #pragma unroll
        for (int hp = 0; hp < 8; hp++) {
            g[hp] = geom2[hp * 260 + tt];
            const float2 gp = unpack2(g[hp]);
            const float ax = lrelu(qf - nk[hp]     - gp.x);
            const float ay = lrelu(qf - nk[hp + 8] - gp.y);
            __nv_bfloat16 hx = __float2bfloat16(ax);
            __nv_bfloat16 hy = __float2bfloat16(ay);
            aH[ hp      * 264 + tt] = hx;
            aH[(hp + 8) * 264 + tt] = hy;
            aL[ hp      * 264 + tt] = __float2bfloat16(ax - __bfloat162float(hx));
            aL[(hp + 8) * 264 + tt] = __float2bfloat16(ay - __bfloat162float(hy));
        }
        HBAR(bid);

        // stage 4: logits1 partials via mma. Warp ww does K-slice c in
        // [32ww, 32ww+32); A rows = h (gid, gid+8); B = Wa1 fragments (regs).
        {
            float acc[4][4];
            #pragma unroll
            for (int nt = 0; nt < 4; nt++)
                #pragma unroll
                for (int r = 0; r < 4; r++) acc[nt][r] = 0.f;

            #pragma unroll
            for (int s = 0; s < 2; s++) {
                const int kk = ww * 32 + s * 16 + tq * 2;
                unsigned ah[4], al[4];
                ah[0] = *(const unsigned*)&aH[ gid      * 264 + kk];
                ah[1] = *(const unsigned*)&aH[(gid + 8) * 264 + kk];
                ah[2] = *(const unsigned*)&aH[ gid      * 264 + kk + 8];
                ah[3] = *(const unsigned*)&aH[(gid + 8) * 264 + kk + 8];
                al[0] = *(const unsigned*)&aL[ gid      * 264 + kk];
                al[1] = *(const unsigned*)&aL[(gid + 8) * 264 + kk];
                al[2] = *(const unsigned*)&aL[ gid      * 264 + kk + 8];
                al[3] = *(const unsigned*)&aL[(gid + 8) * 264 + kk + 8];
                #pragma unroll
                for (int nt = 0; nt < 4; nt++) {
                    mma_bf16(acc[nt], ah, wbh[nt][s]);
                    mma_bf16(acc[nt], ah, wbl[nt][s]);
                    mma_bf16(acc[nt], al, wbh[nt][s]);
                }
            }
            // store partials h-paired: rows (gid, gid+8)
            #pragma unroll
            for (int nt = 0; nt < 4; nt++) {
                const int m = nt * 8 + tq * 2;
                ulonglong2 v;
                v.x = pack2(acc[nt][0], acc[nt][2]);
                v.y = pack2(acc[nt][1], acc[nt][3]);
                *(ulonglong2*)&partu[(ww * 8 + gid) * 34 + m] = v;
            }
        }
        HBAR(bid);

        // stage 4b: reduce 8 warp partials, bias, lrelu -> l1s rows (hp, hp+8)
        {
            const int hp = tt >> 5;
            const int m  = tt & 31;
            const float b = ba1s[m];
            ull s = pack2(b, b);
            #pragma unroll
            for (int w8 = 0; w8 < 8; w8++)
                s = addf2(s, partu[(w8 * 8 + hp) * 34 + m]);
            float2 v = unpack2(s);
            l1s[ hp      * 34 + m] = lrelu(v.x);
            l1s[(hp + 8) * 34 + m] = lrelu(v.y);
        }
        HBAR(bid);

        // stage 5: logits2 = l1 @ Wa2 + ba2
        {
            const int h  = tt >> 4;
            const int m0 = (tt & 15) * 2;
            ull acc01 = pack2(ba2s[m0], ba2s[m0 + 1]);
            const float* lrow = l1s + h * 34;
            #pragma unroll
            for (int jj = 0; jj < 32; jj++) {
                const float lv = lrow[jj];
                ull w = *(const ull*)(Wa2s + jj * 32 + m0);
                acc01 = ffma2(pack2(lv, lv), w, acc01);
            }
            float2 r = unpack2(acc01);
            l2s[h * 34 + m0    ] = r.x;
            l2s[h * 34 + m0 + 1] = r.y;
        }
        HBAR(bid);

        // stage 6: softmax over h; attn pairs (hp, hp+8)
        if (tt < 32) {
            float vals[16];
            float mx = -3.4e38f;
            #pragma unroll
            for (int h = 0; h < 16; h++) {
                vals[h] = l2s[h * 34 + tt];
                mx = fmaxf(mx, vals[h]);
            }
            float s = 0.f;
            #pragma unroll
            for (int h = 0; h < 16; h++) {
                vals[h] = __expf(vals[h] - mx);
                s += vals[h];
            }
            const float inv = 1.f / s;
            #pragma unroll
            for (int hp = 0; hp < 8; hp++)
                attn2[hp * 34 + tt] = pack2(vals[hp] * inv, vals[hp + 8] * inv);
        }
        HBAR(bid);

        // stage 7: out[c] = sum_h (nv[h]-geom[h]) * attn[h][c>>3]
        {
            const int mg = tt >> 3;
            ull acc2p = 0ull;
            #pragma unroll
            for (int hp = 0; hp < 8; hp++) {
                const float2 gp = unpack2(g[hp]);
                ull vm = pack2(nv[hp] - gp.x, nv[hp + 8] - gp.y);
                acc2p = ffma2(vm, attn2[hp * 34 + mg], acc2p);
            }
            float2 r = unpack2(acc2p);
            if (do_store) out[n * 256 + tt] = r.x + r.y;
        }
    }
}

// --------------------------- launch ------------------------------------------
extern "C" void kernel_launch(void* const* d_in, const int* in_sizes, int n_in,
                              void* d_out, int out_size) {
    const float* q_pts   = (const float*)d_in[0];
    const float* s_pts   = (const float*)d_in[1];
    const float* s_feats = (const float*)d_in[2];
    const void*  nb_inds = d_in[3];
    const float* Wq = (const float*)d_in[4];
    const float* bq = (const float*)d_in[5];
    const float* Wk = (const float*)d_in[6];
    const float* bk = (const float*)d_in[7];
    const float* Wv = (const float*)d_in[8];
    const float* bv = (const float*)d_in[9];
    const float* Wd1 = (const float*)d_in[10];
    const float* bd1 = (const float*)d_in[11];
    const float* Wd2 = (const float*)d_in[12];
    const float* bd2 = (const float*)d_in[13];
    const float* Wa1 = (const float*)d_in[14];
    const float* ba1 = (const float*)d_in[15];
    const float* Wa2 = (const float*)d_in[16];
    const float* ba2 = (const float*)d_in[17];
    float* out = (float*)d_out;

    const int N = in_sizes[0] / 3;

    cudaFuncSetAttribute(pt_fused_attn,
                         cudaFuncAttributeMaxDynamicSharedMemorySize, SMEM_BYTES);
    cudaFuncSetAttribute(pt_qkv_gemm_mma,
                         cudaFuncAttributeMaxDynamicSharedMemorySize, GEMM_SMEM);

    pt_detect_idx<<<1, 256>>>((const unsigned*)nb_inds);
    pt_convert_idx<<<(N * HH + 255) / 256, 256>>>(nb_inds, N * HH);
    pt_prepack_w<<<(768 * 256 + 255) / 256, 256>>>(Wq, bq, Wk, bk, Wv, bv, Wd2, Wa1);
    pt_cvt_a<<<(MPAD * 256) / 256, 256>>>(s_feats, N);

    dim3 ggrid((N + 127) / 128, 6);
    pt_qkv_gemm_mma<<<ggrid, 256, GEMM_SMEM>>>(N);

    int fgrid = 148;
    if (fgrid * 2 > N) fgrid = (N + 1) / 2;
    pt_fused_attn<<<fgrid, 512, SMEM_BYTES>>>(q_pts, s_pts,
                                              Wd1, bd1, bd2,
                                              ba1, Wa2, ba2,
                                              out, N);
}

// round 9
// speedup vs baseline: 3.2878x; 1.0421x over previous
#include <cuda_runtime.h>
#include <cuda_bf16.h>

// ---------------------------------------------------------------------------
// point_transformer, Round 9  (R8 + corrected Wa1-lo smem fill)
//   - fused attention: THREE independent 256-thread halves (768 thr, 24 warps)
//     * geom2/partu smem overlay, Wa1-lo frags in smem, nv prefetch deferred
//   - GEMM unchanged (cp.async double-buffered mma.sync)
// ---------------------------------------------------------------------------
#define NMAX 50000
#define MPAD 50048     // 391 * 128
#define HH   16

typedef unsigned long long ull;

__device__ float g_qkv[NMAX * 768];     // [n][0:256)=q [256:512)=k [512:768)=v
__device__ int   g_inds[NMAX * HH];
__device__ int   g_is32;
__device__ float g_bcat[768];
__device__ __nv_bfloat16 g_ahi[MPAD * 256];
__device__ __nv_bfloat16 g_alo[MPAD * 256];
__device__ __nv_bfloat16 g_whiT[768 * 256];    // Wcat^T: [n][k]
__device__ __nv_bfloat16 g_wloT[768 * 256];
__device__ __nv_bfloat16 g_wd2hiT[256 * 64];   // Wd2^T: [c][d]
__device__ __nv_bfloat16 g_wd2loT[256 * 64];
__device__ __nv_bfloat16 g_wa1hiT[32 * 256];   // Wa1^T: [m][c]
__device__ __nv_bfloat16 g_wa1loT[32 * 256];

static __device__ __forceinline__ float lrelu(float x) {
    return fmaxf(x, 0.1f * x);
}
static __device__ __forceinline__ ull ffma2(ull a, ull b, ull c) {
    ull d;
    asm("fma.rn.f32x2 %0, %1, %2, %3;" : "=l"(d) : "l"(a), "l"(b), "l"(c));
    return d;
}
static __device__ __forceinline__ ull addf2(ull a, ull b) {
    ull d;
    asm("add.rn.f32x2 %0, %1, %2;" : "=l"(d) : "l"(a), "l"(b));
    return d;
}
static __device__ __forceinline__ ull pack2(float x, float y) {
    ull r;
    asm("mov.b64 %0, {%1, %2};" : "=l"(r) : "f"(x), "f"(y));
    return r;
}
static __device__ __forceinline__ float2 unpack2(ull v) {
    float2 f;
    asm("mov.b64 {%0, %1}, %2;" : "=f"(f.x), "=f"(f.y) : "l"(v));
    return f;
}
static __device__ __forceinline__ void mma_bf16(float* d, const unsigned* a,
                                                const unsigned* b) {
    asm volatile(
        "mma.sync.aligned.m16n8k16.row.col.f32.bf16.bf16.f32 "
        "{%0,%1,%2,%3}, {%4,%5,%6,%7}, {%8,%9}, {%0,%1,%2,%3};"
        : "+f"(d[0]), "+f"(d[1]), "+f"(d[2]), "+f"(d[3])
        : "r"(a[0]), "r"(a[1]), "r"(a[2]), "r"(a[3]), "r"(b[0]), "r"(b[1]));
}
static __device__ __forceinline__ ull pack4bf_hi(float a, float b, float c, float d) {
    unsigned short u0 = __bfloat16_as_ushort(__float2bfloat16(a));
    unsigned short u1 = __bfloat16_as_ushort(__float2bfloat16(b));
    unsigned short u2 = __bfloat16_as_ushort(__float2bfloat16(c));
    unsigned short u3 = __bfloat16_as_ushort(__float2bfloat16(d));
    return (ull)u0 | ((ull)u1 << 16) | ((ull)u2 << 32) | ((ull)u3 << 48);
}
static __device__ __forceinline__ unsigned smem_u32(const void* p) {
    unsigned a;
    asm("{ .reg .u64 t; cvta.to.shared.u64 t, %1; cvt.u32.u64 %0, t; }"
        : "=r"(a) : "l"(p));
    return a;
}
static __device__ __forceinline__ void cp16(unsigned smaddr, const void* g) {
    asm volatile("cp.async.cg.shared.global [%0], [%1], 16;"
                 :: "r"(smaddr), "l"(g) : "memory");
}
#define CP_COMMIT() asm volatile("cp.async.commit_group;" ::: "memory")
#define CP_WAIT(n)  asm volatile("cp.async.wait_group %0;" :: "n"(n) : "memory")

// --------------------------- index dtype handling ---------------------------
__global__ void pt_detect_idx(const unsigned* __restrict__ w) {
    __shared__ int flag;
    if (threadIdx.x == 0) flag = 0;
    __syncthreads();
    unsigned v = w[2 * threadIdx.x + 1];   // int64: odd words are zero
    if (v != 0u) flag = 1;
    __syncthreads();
    if (threadIdx.x == 0) g_is32 = flag;
}

__global__ void pt_convert_idx(const void* __restrict__ p, int total) {
    int i = blockIdx.x * blockDim.x + threadIdx.x;
    if (i >= total) return;
    if (g_is32) g_inds[i] = ((const int*)p)[i];
    else        g_inds[i] = (int)(((const long long*)p)[i]);
}

// --------------------------- prepacks ---------------------------------------
__global__ void pt_prepack_w(const float* __restrict__ Wq, const float* __restrict__ bq,
                             const float* __restrict__ Wk, const float* __restrict__ bk,
                             const float* __restrict__ Wv, const float* __restrict__ bv,
                             const float* __restrict__ Wd2, const float* __restrict__ Wa1) {
    int i = blockIdx.x * blockDim.x + threadIdx.x;
    if (i < 768 * 256) {
        int n = i >> 8, k = i & 255;
        float w;
        if      (n < 256) w = Wq[k * 256 + n];
        else if (n < 512) w = Wk[k * 256 + (n - 256)];
        else              w = Wv[k * 256 + (n - 512)];
        __nv_bfloat16 hi = __float2bfloat16(w);
        float lo = w - __bfloat162float(hi);
        g_whiT[i] = hi;
        g_wloT[i] = __float2bfloat16(lo);
    }
    if (i < 256 * 64) {
        int c = i >> 6, d = i & 63;
        float w = Wd2[d * 256 + c];
        __nv_bfloat16 hi = __float2bfloat16(w);
        float lo = w - __bfloat162float(hi);
        g_wd2hiT[i] = hi;
        g_wd2loT[i] = __float2bfloat16(lo);
    }
    if (i < 32 * 256) {
        int m = i >> 8, k = i & 255;
        float w = Wa1[k * 32 + m];
        __nv_bfloat16 hi = __float2bfloat16(w);
        float lo = w - __bfloat162float(hi);
        g_wa1hiT[i] = hi;
        g_wa1loT[i] = __float2bfloat16(lo);
    }
    if (i < 768) {
        g_bcat[i] = (i < 256) ? bq[i] : (i < 512 ? bk[i - 256] : bv[i - 512]);
    }
}

__global__ void pt_cvt_a(const float* __restrict__ A, int M) {
    int i = blockIdx.x * blockDim.x + threadIdx.x;
    if (i >= MPAD * 256) return;
    int row = i >> 8;
    float a = (row < M) ? A[i] : 0.f;
    __nv_bfloat16 hi = __float2bfloat16(a);
    float lo = a - __bfloat162float(hi);
    g_ahi[i] = hi;
    g_alo[i] = __float2bfloat16(lo);
}

// --------------------------- mma.sync QKV GEMM (cp.async x2 buf) ------------
#define SK 40
#define TILE_BYTES  (128 * SK * 2)      // 10240
#define STAGE_BYTES (4 * TILE_BYTES)    // 40960: Ahi|Alo|Bhi|Blo
#define GEMM_SMEM   (2 * STAGE_BYTES)   // 81920

extern __shared__ char sm_raw[];

__global__ void __launch_bounds__(256, 2)
pt_qkv_gemm_mma(int M) {
    char* gsm = sm_raw;
    const unsigned sbase = smem_u32(gsm);

    const int t    = threadIdx.x;
    const int warp = t >> 5;
    const int lane = t & 31;
    const int gid  = lane >> 2;
    const int tq   = lane & 3;
    const int m0 = blockIdx.x * 128;
    const int n0 = blockIdx.y * 128;
    const int mw = (warp & 1) * 64;
    const int nw = (warp >> 1) * 32;

    const int row0 = t >> 2;
    const int kq0  = t & 3;
    const int row1 = (t + 256) >> 2;
    const int kq1  = kq0;

    float acc[4][4][4];
    #pragma unroll
    for (int mt = 0; mt < 4; mt++)
        #pragma unroll
        for (int nt = 0; nt < 4; nt++)
            #pragma unroll
            for (int r = 0; r < 4; r++) acc[mt][nt][r] = 0.f;

    auto issue = [&](int kc, int buf) {
        const int k0 = kc * 32;
        const unsigned sb = sbase + buf * STAGE_BYTES;
        {
            unsigned dst = sb + (row0 * SK + kq0 * 8) * 2;
            int asrc = (m0 + row0) * 256 + k0 + kq0 * 8;
            int bsrc = (n0 + row0) * 256 + k0 + kq0 * 8;
            cp16(dst + 0 * TILE_BYTES, &g_ahi[asrc]);
            cp16(dst + 1 * TILE_BYTES, &g_alo[asrc]);
            cp16(dst + 2 * TILE_BYTES, &g_whiT[bsrc]);
            cp16(dst + 3 * TILE_BYTES, &g_wloT[bsrc]);
        }
        {
            unsigned dst = sb + (row1 * SK + kq1 * 8) * 2;
            int asrc = (m0 + row1) * 256 + k0 + kq1 * 8;
            int bsrc = (n0 + row1) * 256 + k0 + kq1 * 8;
            cp16(dst + 0 * TILE_BYTES, &g_ahi[asrc]);
            cp16(dst + 1 * TILE_BYTES, &g_alo[asrc]);
            cp16(dst + 2 * TILE_BYTES, &g_whiT[bsrc]);
            cp16(dst + 3 * TILE_BYTES, &g_wloT[bsrc]);
        }
        CP_COMMIT();
    };

    issue(0, 0);

    for (int kc = 0; kc < 8; kc++) {
        if (kc < 7) issue(kc + 1, (kc + 1) & 1);
        if (kc < 7) { CP_WAIT(1); } else { CP_WAIT(0); }
        __syncthreads();

        char* base = gsm + (kc & 1) * STAGE_BYTES;
        const __nv_bfloat16* smAhi = (const __nv_bfloat16*)(base);
        const __nv_bfloat16* smAlo = (const __nv_bfloat16*)(base + 1 * TILE_BYTES);
        const __nv_bfloat16* smBhi = (const __nv_bfloat16*)(base + 2 * TILE_BYTES);
        const __nv_bfloat16* smBlo = (const __nv_bfloat16*)(base + 3 * TILE_BYTES);

        #pragma unroll
        for (int ks = 0; ks < 2; ks++) {
            const int kk = ks * 16 + tq * 2;
            unsigned bh[4][2], bl[4][2];
            #pragma unroll
            for (int nt = 0; nt < 4; nt++) {
                const int nr = nw + nt * 8 + gid;
                bh[nt][0] = *(const unsigned*)&smBhi[nr * SK + kk];
                bh[nt][1] = *(const unsigned*)&smBhi[nr * SK + kk + 8];
                bl[nt][0] = *(const unsigned*)&smBlo[nr * SK + kk];
                bl[nt][1] = *(const unsigned*)&smBlo[nr * SK + kk + 8];
            }
            #pragma unroll
            for (int mt = 0; mt < 4; mt++) {
                const int mr = mw + mt * 16 + gid;
                unsigned ah[4], al[4];
                ah[0] = *(const unsigned*)&smAhi[ mr      * SK + kk];
                ah[1] = *(const unsigned*)&smAhi[(mr + 8) * SK + kk];
                ah[2] = *(const unsigned*)&smAhi[ mr      * SK + kk + 8];
                ah[3] = *(const unsigned*)&smAhi[(mr + 8) * SK + kk + 8];
                al[0] = *(const unsigned*)&smAlo[ mr      * SK + kk];
                al[1] = *(const unsigned*)&smAlo[(mr + 8) * SK + kk];
                al[2] = *(const unsigned*)&smAlo[ mr      * SK + kk + 8];
                al[3] = *(const unsigned*)&smAlo[(mr + 8) * SK + kk + 8];
                #pragma unroll
                for (int nt = 0; nt < 4; nt++) {
                    mma_bf16(acc[mt][nt], ah, bh[nt]);
                    mma_bf16(acc[mt][nt], ah, bl[nt]);
                    mma_bf16(acc[mt][nt], al, bh[nt]);
                }
            }
        }
        __syncthreads();
    }

    #pragma unroll
    for (int mt = 0; mt < 4; mt++) {
        const int r0 = m0 + mw + mt * 16 + gid;
        const int r1 = r0 + 8;
        #pragma unroll
        for (int nt = 0; nt < 4; nt++) {
            const int col = n0 + nw + nt * 8 + tq * 2;
            const float b0 = g_bcat[col], b1 = g_bcat[col + 1];
            if (r0 < M) {
                float2 o = make_float2(acc[mt][nt][0] + b0, acc[mt][nt][1] + b1);
                *(float2*)&g_qkv[r0 * 768 + col] = o;
            }
            if (r1 < M) {
                float2 o = make_float2(acc[mt][nt][2] + b0, acc[mt][nt][3] + b1);
                *(float2*)&g_qkv[r1 * 768 + col] = o;
            }
        }
    }
}

// --------------------------- fused attention --------------------------------
// 768 threads = three independent 256-thread halves (named barriers 1/2/3).
// h-pair convention: pair hp = (h=hp, h=hp+8).
#define OFF_WD2H  0        // bf16 [256][72] -> 9216 floats
#define OFF_WD2L  9216
#define OFF_WA1L  18432    // bf16 [32][264] -> 4224 floats
#define OFF_WA2   22656    // [32][32]
#define OFF_WD1   23680
#define OFF_BD1   23872
#define OFF_BD2   23936
#define OFF_BA1   24192
#define OFF_BA2   24224
#define WEIGHT_FLOATS 24256

#define PP_AH     0        // bf16 [16][264] = 2112 floats
#define PP_AL     2112     // bf16 [16][264]
#define PP_GP     4224     // OVERLAY: geom2 ull[8][260] (4160) / partu ull[8][8][34] (4352)
#define PP_L1     8576     // [16][34]
#define PP_L2     9120     // [16][34]
#define PP_ATTN   9664     // ull [8][34] = 544 floats
#define PP_INDS   10208    // 16 ints
#define PP_QPT    10224    // 3 floats + pad
#define PP_FLOATS 10228

#define SMEM_FLOATS (WEIGHT_FLOATS + 3 * PP_FLOATS)
#define SMEM_BYTES  (SMEM_FLOATS * 4)

#define HBAR(id) asm volatile("bar.sync %0, 256;" :: "r"(id) : "memory")

__global__ void __launch_bounds__(768, 1)
pt_fused_attn(const float* __restrict__ q_pts,
              const float* __restrict__ s_pts,
              const float* __restrict__ Wd1, const float* __restrict__ bd1,
              const float* __restrict__ bd2,
              const float* __restrict__ ba1,
              const float* __restrict__ Wa2, const float* __restrict__ ba2,
              float* __restrict__ out, int N) {
    float* sm = (float*)sm_raw;
    __nv_bfloat16* Wd2THs = (__nv_bfloat16*)(sm + OFF_WD2H);  // [256 c][72 d]
    __nv_bfloat16* Wd2TLs = (__nv_bfloat16*)(sm + OFF_WD2L);
    __nv_bfloat16* Wa1Ls  = (__nv_bfloat16*)(sm + OFF_WA1L);  // [32 m][264 c]
    float* Wa2s = sm + OFF_WA2;
    float* Wd1s = sm + OFF_WD1;
    float* bd1s = sm + OFF_BD1;
    float* bd2s = sm + OFF_BD2;
    float* ba1s = sm + OFF_BA1;
    float* ba2s = sm + OFF_BA2;

    const int t   = threadIdx.x;
    const int pid = t >> 8;         // 0,1,2
    const int tt  = t & 255;
    const int ww  = (t >> 5) & 7;   // warp in half: owns c-slice [32ww, 32ww+32)
    const int l   = t & 31;
    const int gid = l >> 2;
    const int tq  = l & 3;
    const int bid = pid + 1;

    float* pp     = sm + WEIGHT_FLOATS + pid * PP_FLOATS;
    __nv_bfloat16* aH = (__nv_bfloat16*)(pp + PP_AH);   // [16 h][264 c]
    __nv_bfloat16* aL = (__nv_bfloat16*)(pp + PP_AL);
    ull*   geom2  = (ull*)(pp + PP_GP);     // [8 hp][260 c]   (overlay)
    ull*   partu  = (ull*)(pp + PP_GP);     // [(ww*8+hp)*34+m] (overlay)
    float* l1s    = pp + PP_L1;
    float* l2s    = pp + PP_L2;
    ull*   attn2  = (ull*)(pp + PP_ATTN);
    int*   inds_s = (int*)(pp + PP_INDS);
    float* qptf   = pp + PP_QPT;

    // persistent Wa1 HI B-fragments in registers; LO stays in smem
    unsigned wbh[4][2][2];
    #pragma unroll
    for (int nt = 0; nt < 4; nt++)
        #pragma unroll
        for (int s = 0; s < 2; s++) {
            const int m  = nt * 8 + gid;
            const int k0 = ww * 32 + s * 16 + tq * 2;
            wbh[nt][s][0] = *(const unsigned*)&g_wa1hiT[m * 256 + k0];
            wbh[nt][s][1] = *(const unsigned*)&g_wa1hiT[m * 256 + k0 + 8];
        }

    // stage 0: weights -> shared (all 768 threads)
    for (int i = t; i < 256 * 16; i += 768) {
        int n = i >> 4, k4 = (i & 15) * 4;
        *(ull*)&Wd2THs[n * 72 + k4] = ((const ull*)g_wd2hiT)[i];
        *(ull*)&Wd2TLs[n * 72 + k4] = ((const ull*)g_wd2loT)[i];
    }
    // Wa1 lo: 32 rows x 256 bf16 = 2048 ulls (4 bf16 each)
    for (int i = t; i < 2048; i += 768) {
        int m = i >> 6, u = i & 63;
        *(ull*)&Wa1Ls[m * 264 + u * 4] = ((const ull*)g_wa1loT)[i];
    }
    for (int i = t; i < 1024; i += 768) Wa2s[i] = Wa2[i];
    if (t < 192) Wd1s[t] = Wd1[t];
    if (t < 64)  bd1s[t] = bd1[t];
    if (t < 256) bd2s[t] = bd2[t];
    if (t < 32) { ba1s[t] = ba1[t]; ba2s[t] = ba2[t]; }
    __syncthreads();

    for (int n3 = blockIdx.x; n3 * 3 < N; n3 += gridDim.x) {
        const int nreq = n3 * 3 + pid;
        const int n = (nreq < N) ? nreq : (N - 1);
        const bool do_store = (nreq < N);

        if (tt < 16) inds_s[tt] = g_inds[n * 16 + tt];
        if (tt < 3)  qptf[tt]   = q_pts[n * 3 + tt];
        HBAR(bid);

        // prefetch nk + qf (dead after stage 3)
        float nk[16];
        const float qf = g_qkv[inds_s[0] * 768 + tt];
        #pragma unroll
        for (int h = 0; h < 16; h++)
            nk[h] = g_qkv[inds_s[h] * 768 + 256 + tt];

        // stage 1: hidden = lrelu(rel @ Wd1 + bd1), bf16 hi/lo (stride 72 in aH/aL)
        {
            const int h  = tt >> 4;
            const int d0 = (tt & 15) << 2;
            const int j  = inds_s[h];
            const float rx = s_pts[j * 3 + 0] - qptf[0];
            const float ry = s_pts[j * 3 + 1] - qptf[1];
            const float rz = s_pts[j * 3 + 2] - qptf[2];
            float vv[4], vh[4], vl[4];
            #pragma unroll
            for (int i = 0; i < 4; i++) {
                const int d = d0 + i;
                float v = rx * Wd1s[d] + ry * Wd1s[64 + d] + rz * Wd1s[128 + d] + bd1s[d];
                vv[i] = lrelu(v);
                vh[i] = __bfloat162float(__float2bfloat16(vv[i]));
                vl[i] = vv[i] - vh[i];
            }
            *(ull*)&aH[h * 72 + d0] = pack4bf_hi(vh[0], vh[1], vh[2], vh[3]);
            *(ull*)&aL[h * 72 + d0] = pack4bf_hi(vl[0], vl[1], vl[2], vl[3]);
        }
        HBAR(bid);

        // stage 2: geom = hid @ Wd2 via mma (hi/lo split); D rows (gid, gid+8)
        {
            float acc[4][4];
            #pragma unroll
            for (int nt = 0; nt < 4; nt++)
                #pragma unroll
                for (int r = 0; r < 4; r++) acc[nt][r] = 0.f;

            #pragma unroll
            for (int kc = 0; kc < 4; kc++) {
                const int k0 = kc * 16;
                unsigned ah[4], al[4];
                ah[0] = *(const unsigned*)&aH[ gid      * 72 + k0 + tq * 2];
                ah[1] = *(const unsigned*)&aH[(gid + 8) * 72 + k0 + tq * 2];
                ah[2] = *(const unsigned*)&aH[ gid      * 72 + k0 + 8 + tq * 2];
                ah[3] = *(const unsigned*)&aH[(gid + 8) * 72 + k0 + 8 + tq * 2];
                al[0] = *(const unsigned*)&aL[ gid      * 72 + k0 + tq * 2];
                al[1] = *(const unsigned*)&aL[(gid + 8) * 72 + k0 + tq * 2];
                al[2] = *(const unsigned*)&aL[ gid      * 72 + k0 + 8 + tq * 2];
                al[3] = *(const unsigned*)&aL[(gid + 8) * 72 + k0 + 8 + tq * 2];
                #pragma unroll
                for (int nt = 0; nt < 4; nt++) {
                    const int nr = ww * 32 + nt * 8 + gid;
                    unsigned bh[2], bl[2];
                    bh[0] = *(const unsigned*)&Wd2THs[nr * 72 + k0 + tq * 2];
                    bh[1] = *(const unsigned*)&Wd2THs[nr * 72 + k0 + 8 + tq * 2];
                    bl[0] = *(const unsigned*)&Wd2TLs[nr * 72 + k0 + tq * 2];
                    bl[1] = *(const unsigned*)&Wd2TLs[nr * 72 + k0 + 8 + tq * 2];
                    mma_bf16(acc[nt], ah, bh);
                    mma_bf16(acc[nt], ah, bl);
                    mma_bf16(acc[nt], al, bh);
                }
            }
            #pragma unroll
            for (int nt = 0; nt < 4; nt++) {
                const int c0 = ww * 32 + nt * 8 + tq * 2;
                const float b0 = bd2s[c0], b1 = bd2s[c0 + 1];
                geom2[gid * 260 + c0    ] = pack2(acc[nt][0] + b0, acc[nt][2] + b0);
                geom2[gid * 260 + c0 + 1] = pack2(acc[nt][1] + b1, acc[nt][3] + b1);
            }
        }
        HBAR(bid);

        // stage 3: a = lrelu(qf - nk - geom); store bf16 hi/lo [16][264]
        ull g[8];
        #pragma unroll
        for (int hp = 0; hp < 8; hp++) {
            g[hp] = geom2[hp * 260 + tt];
            const float2 gp = unpack2(g[hp]);
            const float ax = lrelu(qf - nk[hp]     - gp.x);
            const float ay = lrelu(qf - nk[hp + 8] - gp.y);
            __nv_bfloat16 hx = __float2bfloat16(ax);
            __nv_bfloat16 hy = __float2bfloat16(ay);
            aH[ hp      * 264 + tt] = hx;
            aH[(hp + 8) * 264 + tt] = hy;
            aL[ hp      * 264 + tt] = __float2bfloat16(ax - __bfloat162float(hx));
            aL[(hp + 8) * 264 + tt] = __float2bfloat16(ay - __bfloat162float(hy));
        }
        HBAR(bid);

        // stage 4: logits1 partials via mma (Wa1 hi in regs, lo in smem)
        {
            float acc[4][4];
            #pragma unroll
            for (int nt = 0; nt < 4; nt++)
                #pragma unroll
                for (int r = 0; r < 4; r++) acc[nt][r] = 0.f;

            #pragma unroll
            for (int s = 0; s < 2; s++) {
                const int kk = ww * 32 + s * 16 + tq * 2;
                unsigned ah[4], al[4];
                ah[0] = *(const unsigned*)&aH[ gid      * 264 + kk];
                ah[1] = *(const unsigned*)&aH[(gid + 8) * 264 + kk];
                ah[2] = *(const unsigned*)&aH[ gid      * 264 + kk + 8];
                ah[3] = *(const unsigned*)&aH[(gid + 8) * 264 + kk + 8];
                al[0] = *(const unsigned*)&aL[ gid      * 264 + kk];
                al[1] = *(const unsigned*)&aL[(gid + 8) * 264 + kk];
                al[2] = *(const unsigned*)&aL[ gid      * 264 + kk + 8];
                al[3] = *(const unsigned*)&aL[(gid + 8) * 264 + kk + 8];
                #pragma unroll
                for (int nt = 0; nt < 4; nt++) {
                    const int m = nt * 8 + gid;
                    unsigned bl[2];
                    bl[0] = *(const unsigned*)&Wa1Ls[m * 264 + ww * 32 + s * 16 + tq * 2];
                    bl[1] = *(const unsigned*)&Wa1Ls[m * 264 + ww * 32 + s * 16 + tq * 2 + 8];
                    mma_bf16(acc[nt], ah, wbh[nt][s]);
                    mma_bf16(acc[nt], ah, bl);
                    mma_bf16(acc[nt], al, wbh[nt][s]);
                }
            }
            #pragma unroll
            for (int nt = 0; nt < 4; nt++) {
                const int m = nt * 8 + tq * 2;
                ulonglong2 v;
                v.x = pack2(acc[nt][0], acc[nt][2]);
                v.y = pack2(acc[nt][1], acc[nt][3]);
                *(ulonglong2*)&partu[(ww * 8 + gid) * 34 + m] = v;
            }
        }

        // prefetch nv (acc regs dead; hidden behind barrier + stages 4b-6)
        float nv[16];
        #pragma unroll
        for (int h = 0; h < 16; h++)
            nv[h] = g_qkv[inds_s[h] * 768 + 512 + tt];
        HBAR(bid);

        // stage 4b: reduce 8 warp partials, bias, lrelu -> l1s rows (hp, hp+8)
        {
            const int hp = tt >> 5;
            const int m  = tt & 31;
            const float b = ba1s[m];
            ull s = pack2(b, b);
            #pragma unroll
            for (int w8 = 0; w8 < 8; w8++)
                s = addf2(s, partu[(w8 * 8 + hp) * 34 + m]);
            float2 v = unpack2(s);
            l1s[ hp      * 34 + m] = lrelu(v.x);
            l1s[(hp + 8) * 34 + m] = lrelu(v.y);
        }
        HBAR(bid);

        // stage 5: logits2 = l1 @ Wa2 + ba2
        {
            const int h  = tt >> 4;
            const int m0 = (tt & 15) * 2;
            ull acc01 = pack2(ba2s[m0], ba2s[m0 + 1]);
            const float* lrow = l1s + h * 34;
            #pragma unroll
            for (int jj = 0; jj < 32; jj++) {
                const float lv = lrow[jj];
                ull w = *(const ull*)(Wa2s + jj * 32 + m0);
                acc01 = ffma2(pack2(lv, lv), w, acc01);
            }
            float2 r = unpack2(acc01);
            l2s[h * 34 + m0    ] = r.x;
            l2s[h * 34 + m0 + 1] = r.y;
        }
        HBAR(bid);

        // stage 6: softmax over h; attn pairs (hp, hp+8)
        if (tt < 32) {
            float vals[16];
            float mx = -3.4e38f;
            #pragma unroll
            for (int h = 0; h < 16; h++) {
                vals[h] = l2s[h * 34 + tt];
                mx = fmaxf(mx, vals[h]);
            }
            float s = 0.f;
            #pragma unroll
            for (int h = 0; h < 16; h++) {
                vals[h] = __expf(vals[h] - mx);
                s += vals[h];
            }
            const float inv = 1.f / s;
            #pragma unroll
            for (int hp = 0; hp < 8; hp++)
                attn2[hp * 34 + tt] = pack2(vals[hp] * inv, vals[hp + 8] * inv);
        }
        HBAR(bid);

        // stage 7: out[c] = sum_h (nv[h]-geom[h]) * attn[h][c>>3]
        {
            const int mg = tt >> 3;
            ull acc2p = 0ull;
            #pragma unroll
            for (int hp = 0; hp < 8; hp++) {
                const float2 gp = unpack2(g[hp]);
                ull vm = pack2(nv[hp] - gp.x, nv[hp + 8] - gp.y);
                acc2p = ffma2(vm, attn2[hp * 34 + mg], acc2p);
            }
            float2 r = unpack2(acc2p);
            if (do_store) out[n * 256 + tt] = r.x + r.y;
        }
        HBAR(bid);   // attn2/l-buffers reusable next iteration
    }
}

// --------------------------- launch ------------------------------------------
extern "C" void kernel_launch(void* const* d_in, const int* in_sizes, int n_in,
                              void* d_out, int out_size) {
    const float* q_pts   = (const float*)d_in[0];
    const float* s_pts   = (const float*)d_in[1];
    const float* s_feats = (const float*)d_in[2];
    const void*  nb_inds = d_in[3];
    const float* Wq = (const float*)d_in[4];
    const float* bq = (const float*)d_in[5];
    const float* Wk = (const float*)d_in[6];
    const float* bk = (const float*)d_in[7];
    const float* Wv = (const float*)d_in[8];
    const float* bv = (const float*)d_in[9];
    const float* Wd1 = (const float*)d_in[10];
    const float* bd1 = (const float*)d_in[11];
    const float* Wd2 = (const float*)d_in[12];
    const float* bd2 = (const float*)d_in[13];
    const float* Wa1 = (const float*)d_in[14];
    const float* ba1 = (const float*)d_in[15];
    const float* Wa2 = (const float*)d_in[16];
    const float* ba2 = (const float*)d_in[17];
    float* out = (float*)d_out;

    const int N = in_sizes[0] / 3;

    cudaFuncSetAttribute(pt_fused_attn,
                         cudaFuncAttributeMaxDynamicSharedMemorySize, SMEM_BYTES);
    cudaFuncSetAttribute(pt_qkv_gemm_mma,
                         cudaFuncAttributeMaxDynamicSharedMemorySize, GEMM_SMEM);

    pt_detect_idx<<<1, 256>>>((const unsigned*)nb_inds);
    pt_convert_idx<<<(N * HH + 255) / 256, 256>>>(nb_inds, N * HH);
    pt_prepack_w<<<(768 * 256 + 255) / 256, 256>>>(Wq, bq, Wk, bk, Wv, bv, Wd2, Wa1);
    pt_cvt_a<<<(MPAD * 256) / 256, 256>>>(s_feats, N);

    dim3 ggrid((N + 127) / 128, 6);
    pt_qkv_gemm_mma<<<ggrid, 256, GEMM_SMEM>>>(N);

    int fgrid = 148;
    if (fgrid * 3 > N) fgrid = (N + 2) / 3;
    pt_fused_attn<<<fgrid, 768, SMEM_BYTES>>>(q_pts, s_pts,
                                              Wd1, bd1, bd2,
                                              ba1, Wa2, ba2,
                                              out, N);
}